// round 2
// baseline (speedup 1.0000x reference)
#include <cuda_runtime.h>
#include <cuda_bf16.h>

#define NN   50000
#define NE   800000
#define HIDD 128
#define EIND 273
#define TE   64
#define NT   256

// Scratch (device globals: no allocation allowed)
__device__ float g_agg[(size_t)NN * HIDD];
__device__ float g_cs[NN * 3];
__device__ float g_cnt[NN];

__device__ __forceinline__ float silu_f(float x) {
    return x / (1.0f + __expf(-x));
}

// ---------------- Edge kernel ----------------
// smem layout (floats):
//   s_ein [273][64]   @ 0       (17472)
//   s_w   [16][128]   @ 17472   (2048)
//   s_m1  [64][132]   @ 19520   (8448)
//   s_m   [64][132]   @ 27968   (8448)
//   s_row [64] (int)  @ 36416
//   s_col [64] (int)  @ 36480
//   s_d   [3][64]     @ 36544
//   s_wgt [64]        @ 36736
// total 36800 floats = 147200 bytes
#define EDGE_SMEM_FLOATS 36800
#define EDGE_SMEM_BYTES  (EDGE_SMEM_FLOATS * 4)

extern __shared__ float smem_f[];

__global__ void __launch_bounds__(NT, 1) edge_kernel(
    const float* __restrict__ h, const float* __restrict__ coord,
    const float* __restrict__ eattr, const int* __restrict__ ei,
    const float* __restrict__ We1, const float* __restrict__ be1,
    const float* __restrict__ We2, const float* __restrict__ be2,
    const float* __restrict__ Wc1, const float* __restrict__ bc1,
    const float* __restrict__ Wc2, const float* __restrict__ bc2,
    float* __restrict__ m_out, float* __restrict__ agg,
    float* __restrict__ cs, float* __restrict__ cnt)
{
    float* s_ein = smem_f;
    float* s_w   = smem_f + 17472;
    float* s_m1  = smem_f + 19520;
    float* s_m   = smem_f + 27968;
    int*   s_row = (int*)(smem_f + 36416);
    int*   s_col = (int*)(smem_f + 36480);
    float* s_d   = smem_f + 36544;
    float* s_wgt = smem_f + 36736;

    const int tid   = threadIdx.x;
    const int eb    = blockIdx.x * TE;
    const int lane  = tid & 31;
    const int warp  = tid >> 5;
    const int ebase = warp * 8;

    // Phase 0: indices, displacement, radial
    if (tid < TE) {
        int g = eb + tid;
        int r = ei[g], c = ei[NE + g];
        s_row[tid] = r; s_col[tid] = c;
        float dx = coord[r*3+0] - coord[c*3+0];
        float dy = coord[r*3+1] - coord[c*3+1];
        float dz = coord[r*3+2] - coord[c*3+2];
        s_d[0*64+tid] = dx; s_d[1*64+tid] = dy; s_d[2*64+tid] = dz;
        s_ein[256*64 + tid] = dx*dx + dy*dy + dz*dz;
    }
    __syncthreads();

    // Phase 1: build e_in columns (k-major)
    {
        int e = tid >> 2, q = tid & 3;  // 4 threads per edge
        const float* hr = h + (size_t)s_row[e] * HIDD + q * 32;
        const float* hc = h + (size_t)s_col[e] * HIDD + q * 32;
        #pragma unroll
        for (int i = 0; i < 8; i++) {
            float4 v = *(const float4*)(hr + i*4);
            int k = q*32 + i*4;
            s_ein[(k+0)*64+e] = v.x; s_ein[(k+1)*64+e] = v.y;
            s_ein[(k+2)*64+e] = v.z; s_ein[(k+3)*64+e] = v.w;
        }
        #pragma unroll
        for (int i = 0; i < 8; i++) {
            float4 v = *(const float4*)(hc + i*4);
            int k = 128 + q*32 + i*4;
            s_ein[(k+0)*64+e] = v.x; s_ein[(k+1)*64+e] = v.y;
            s_ein[(k+2)*64+e] = v.z; s_ein[(k+3)*64+e] = v.w;
        }
    }
    for (int idx = tid; idx < TE * 16; idx += NT) {
        int e = idx >> 4, j = idx & 15;
        s_ein[(257+j)*64 + e] = eattr[(size_t)(eb+e)*16 + j];
    }
    __syncthreads();

    float acc[8][4];
    #pragma unroll
    for (int i = 0; i < 8; i++)
        #pragma unroll
        for (int j = 0; j < 4; j++) acc[i][j] = 0.0f;

    // GEMM1: [64 x 273] @ [273 x 128]
    for (int kb = 0; kb < EIND; kb += 16) {
        int kc = min(16, EIND - kb);
        for (int idx = tid; idx < kc * 128; idx += NT)
            s_w[idx] = We1[kb*128 + idx];
        __syncthreads();
        if (kc == 16) {
            #pragma unroll
            for (int k = 0; k < 16; k++) {
                float4 a0 = *(const float4*)&s_ein[(kb+k)*64 + ebase];
                float4 a1 = *(const float4*)&s_ein[(kb+k)*64 + ebase + 4];
                float4 b  = *(const float4*)&s_w[k*128 + lane*4];
                float av[8] = {a0.x,a0.y,a0.z,a0.w,a1.x,a1.y,a1.z,a1.w};
                float bv[4] = {b.x,b.y,b.z,b.w};
                #pragma unroll
                for (int i = 0; i < 8; i++)
                    #pragma unroll
                    for (int j = 0; j < 4; j++)
                        acc[i][j] = fmaf(av[i], bv[j], acc[i][j]);
            }
        } else {
            for (int k = 0; k < kc; k++) {
                float4 a0 = *(const float4*)&s_ein[(kb+k)*64 + ebase];
                float4 a1 = *(const float4*)&s_ein[(kb+k)*64 + ebase + 4];
                float4 b  = *(const float4*)&s_w[k*128 + lane*4];
                float av[8] = {a0.x,a0.y,a0.z,a0.w,a1.x,a1.y,a1.z,a1.w};
                float bv[4] = {b.x,b.y,b.z,b.w};
                #pragma unroll
                for (int i = 0; i < 8; i++)
                    #pragma unroll
                    for (int j = 0; j < 4; j++)
                        acc[i][j] = fmaf(av[i], bv[j], acc[i][j]);
            }
        }
        __syncthreads();
    }

    // Epilogue 1: bias + silu -> s_m1 (edge-major, stride 132)
    {
        float4 b1 = *(const float4*)&be1[lane*4];
        float bv[4] = {b1.x,b1.y,b1.z,b1.w};
        #pragma unroll
        for (int i = 0; i < 8; i++) {
            float4 o;
            o.x = silu_f(acc[i][0] + bv[0]);
            o.y = silu_f(acc[i][1] + bv[1]);
            o.z = silu_f(acc[i][2] + bv[2]);
            o.w = silu_f(acc[i][3] + bv[3]);
            *(float4*)&s_m1[(ebase+i)*132 + lane*4] = o;
        }
    }
    #pragma unroll
    for (int i = 0; i < 8; i++)
        #pragma unroll
        for (int j = 0; j < 4; j++) acc[i][j] = 0.0f;

    // GEMM2: m1 @ We2 (K=128)
    for (int kb = 0; kb < 128; kb += 16) {
        for (int idx = tid; idx < 16 * 128; idx += NT)
            s_w[idx] = We2[kb*128 + idx];
        __syncthreads();
        #pragma unroll
        for (int k = 0; k < 16; k++) {
            float4 b = *(const float4*)&s_w[k*128 + lane*4];
            float bv[4] = {b.x,b.y,b.z,b.w};
            float av[8];
            #pragma unroll
            for (int i = 0; i < 8; i++)
                av[i] = s_m1[(ebase+i)*132 + kb + k];
            #pragma unroll
            for (int i = 0; i < 8; i++)
                #pragma unroll
                for (int j = 0; j < 4; j++)
                    acc[i][j] = fmaf(av[i], bv[j], acc[i][j]);
        }
        __syncthreads();
    }

    // Epilogue 2: bias + silu -> s_m
    {
        float4 b2 = *(const float4*)&be2[lane*4];
        float bv[4] = {b2.x,b2.y,b2.z,b2.w};
        #pragma unroll
        for (int i = 0; i < 8; i++) {
            float4 o;
            o.x = silu_f(acc[i][0] + bv[0]);
            o.y = silu_f(acc[i][1] + bv[1]);
            o.z = silu_f(acc[i][2] + bv[2]);
            o.w = silu_f(acc[i][3] + bv[3]);
            *(float4*)&s_m[(ebase+i)*132 + lane*4] = o;
        }
    }
    #pragma unroll
    for (int i = 0; i < 8; i++)
        #pragma unroll
        for (int j = 0; j < 4; j++) acc[i][j] = 0.0f;

    // GEMM3: m @ Wc1 (K=128), then silu * Wc2 reduce -> per-edge scalar w
    for (int kb = 0; kb < 128; kb += 16) {
        for (int idx = tid; idx < 16 * 128; idx += NT)
            s_w[idx] = Wc1[kb*128 + idx];
        __syncthreads();
        #pragma unroll
        for (int k = 0; k < 16; k++) {
            float4 b = *(const float4*)&s_w[k*128 + lane*4];
            float bv[4] = {b.x,b.y,b.z,b.w};
            float av[8];
            #pragma unroll
            for (int i = 0; i < 8; i++)
                av[i] = s_m[(ebase+i)*132 + kb + k];
            #pragma unroll
            for (int i = 0; i < 8; i++)
                #pragma unroll
                for (int j = 0; j < 4; j++)
                    acc[i][j] = fmaf(av[i], bv[j], acc[i][j]);
        }
        __syncthreads();
    }
    {
        float4 bc = *(const float4*)&bc1[lane*4];
        float4 wc = *(const float4*)&Wc2[lane*4];
        float bc2v = bc2[0];
        float ws[8];
        #pragma unroll
        for (int i = 0; i < 8; i++) {
            float s = silu_f(acc[i][0] + bc.x) * wc.x;
            s = fmaf(silu_f(acc[i][1] + bc.y), wc.y, s);
            s = fmaf(silu_f(acc[i][2] + bc.z), wc.z, s);
            s = fmaf(silu_f(acc[i][3] + bc.w), wc.w, s);
            ws[i] = s;
        }
        #pragma unroll
        for (int off = 16; off >= 1; off >>= 1)
            #pragma unroll
            for (int i = 0; i < 8; i++)
                ws[i] += __shfl_xor_sync(0xFFFFFFFFu, ws[i], off);
        if (lane == 0) {
            #pragma unroll
            for (int i = 0; i < 8; i++)
                s_wgt[ebase + i] = ws[i] + bc2v;
        }
    }
    __syncthreads();

    // Scatter: m to global + agg atomics
    for (int idx = tid; idx < TE * HIDD; idx += NT) {
        int e = idx >> 7, k = idx & 127;
        float v = s_m[e*132 + k];
        m_out[(size_t)(eb+e)*HIDD + k] = v;
        atomicAdd(&agg[(size_t)s_row[e]*HIDD + k], v);
    }
    if (tid < TE) {
        float w = s_wgt[tid];
        int r = s_row[tid];
        atomicAdd(&cs[r*3+0], s_d[0*64+tid] * w);
        atomicAdd(&cs[r*3+1], s_d[1*64+tid] * w);
        atomicAdd(&cs[r*3+2], s_d[2*64+tid] * w);
        atomicAdd(&cnt[r], 1.0f);
    }
}

// ---------------- Node kernel ----------------
// smem floats: s_nin [64][260] @0 (16640), s_w [16][128] @16640 (2048),
//              s_h1 [64][132] @18688 (8448) -> total 27136 floats = 108544 B
#define NODE_SMEM_FLOATS 27136
#define NODE_SMEM_BYTES  (NODE_SMEM_FLOATS * 4)

__global__ void __launch_bounds__(NT, 1) node_kernel(
    const float* __restrict__ h, const float* __restrict__ coord,
    const float* __restrict__ Wn1, const float* __restrict__ bn1,
    const float* __restrict__ Wn2, const float* __restrict__ bn2,
    const float* __restrict__ agg, const float* __restrict__ cs,
    const float* __restrict__ cnt,
    float* __restrict__ h_out, float* __restrict__ c_out)
{
    float* s_nin = smem_f;
    float* s_w   = smem_f + 16640;
    float* s_h1  = smem_f + 18688;

    const int tid   = threadIdx.x;
    const int nb    = blockIdx.x * 64;
    const int lane  = tid & 31;
    const int warp  = tid >> 5;
    const int ebase = warp * 8;

    // Build n_in = [h | agg] (node-major, stride 260)
    for (int idx = tid; idx < 64 * 64; idx += NT) {
        int n = idx >> 6, f = idx & 63;
        int node = nb + n;
        float4 v = make_float4(0.f, 0.f, 0.f, 0.f);
        if (node < NN) {
            if (f < 32) v = *(const float4*)(h + (size_t)node*HIDD + f*4);
            else        v = *(const float4*)(agg + (size_t)node*HIDD + (f-32)*4);
        }
        *(float4*)&s_nin[n*260 + f*4] = v;
    }
    __syncthreads();

    float acc[8][4];
    #pragma unroll
    for (int i = 0; i < 8; i++)
        #pragma unroll
        for (int j = 0; j < 4; j++) acc[i][j] = 0.0f;

    // GEMM A: n_in @ Wn1 (K=256)
    for (int kb = 0; kb < 256; kb += 16) {
        for (int idx = tid; idx < 16 * 128; idx += NT)
            s_w[idx] = Wn1[kb*128 + idx];
        __syncthreads();
        #pragma unroll
        for (int k = 0; k < 16; k++) {
            float4 b = *(const float4*)&s_w[k*128 + lane*4];
            float bv[4] = {b.x,b.y,b.z,b.w};
            float av[8];
            #pragma unroll
            for (int i = 0; i < 8; i++)
                av[i] = s_nin[(ebase+i)*260 + kb + k];
            #pragma unroll
            for (int i = 0; i < 8; i++)
                #pragma unroll
                for (int j = 0; j < 4; j++)
                    acc[i][j] = fmaf(av[i], bv[j], acc[i][j]);
        }
        __syncthreads();
    }
    {
        float4 b1 = *(const float4*)&bn1[lane*4];
        float bv[4] = {b1.x,b1.y,b1.z,b1.w};
        #pragma unroll
        for (int i = 0; i < 8; i++) {
            float4 o;
            o.x = silu_f(acc[i][0] + bv[0]);
            o.y = silu_f(acc[i][1] + bv[1]);
            o.z = silu_f(acc[i][2] + bv[2]);
            o.w = silu_f(acc[i][3] + bv[3]);
            *(float4*)&s_h1[(ebase+i)*132 + lane*4] = o;
        }
    }
    #pragma unroll
    for (int i = 0; i < 8; i++)
        #pragma unroll
        for (int j = 0; j < 4; j++) acc[i][j] = 0.0f;

    // GEMM B: h1 @ Wn2 (K=128)
    for (int kb = 0; kb < 128; kb += 16) {
        for (int idx = tid; idx < 16 * 128; idx += NT)
            s_w[idx] = Wn2[kb*128 + idx];
        __syncthreads();
        #pragma unroll
        for (int k = 0; k < 16; k++) {
            float4 b = *(const float4*)&s_w[k*128 + lane*4];
            float bv[4] = {b.x,b.y,b.z,b.w};
            float av[8];
            #pragma unroll
            for (int i = 0; i < 8; i++)
                av[i] = s_h1[(ebase+i)*132 + kb + k];
            #pragma unroll
            for (int i = 0; i < 8; i++)
                #pragma unroll
                for (int j = 0; j < 4; j++)
                    acc[i][j] = fmaf(av[i], bv[j], acc[i][j]);
        }
        __syncthreads();
    }
    {
        float4 b2 = *(const float4*)&bn2[lane*4];
        #pragma unroll
        for (int i = 0; i < 8; i++) {
            int node = nb + ebase + i;
            if (node < NN) {
                float4 o;
                o.x = acc[i][0] + b2.x;
                o.y = acc[i][1] + b2.y;
                o.z = acc[i][2] + b2.z;
                o.w = acc[i][3] + b2.w;
                *(float4*)&h_out[(size_t)node*HIDD + lane*4] = o;
            }
        }
    }

    // coord update
    if (tid < 64) {
        int node = nb + tid;
        if (node < NN) {
            float c = cnt[node];
            float dn = fmaxf(c, 1.0f);
            #pragma unroll
            for (int d = 0; d < 3; d++)
                c_out[node*3 + d] = coord[node*3 + d] + cs[node*3 + d] / dn;
        }
    }
}

extern "C" void kernel_launch(void* const* d_in, const int* in_sizes, int n_in,
                              void* d_out, int out_size)
{
    const float* h     = (const float*)d_in[0];
    const float* coord = (const float*)d_in[1];
    const float* eattr = (const float*)d_in[2];
    const int*   ei    = (const int*)d_in[3];
    const float* We1   = (const float*)d_in[4];
    const float* be1   = (const float*)d_in[5];
    const float* We2   = (const float*)d_in[6];
    const float* be2   = (const float*)d_in[7];
    const float* Wn1   = (const float*)d_in[8];
    const float* bn1   = (const float*)d_in[9];
    const float* Wn2   = (const float*)d_in[10];
    const float* bn2   = (const float*)d_in[11];
    const float* Wc1   = (const float*)d_in[12];
    const float* bc1   = (const float*)d_in[13];
    const float* Wc2   = (const float*)d_in[14];
    const float* bc2   = (const float*)d_in[15];

    float* out   = (float*)d_out;
    float* h_out = out;                                 // [NN,128]
    float* c_out = out + (size_t)NN * HIDD;             // [NN,3]
    float* m_out = c_out + (size_t)NN * 3;              // [NE,128]

    void *p_agg, *p_cs, *p_cnt;
    cudaGetSymbolAddress(&p_agg, g_agg);
    cudaGetSymbolAddress(&p_cs, g_cs);
    cudaGetSymbolAddress(&p_cnt, g_cnt);
    cudaMemsetAsync(p_agg, 0, (size_t)NN * HIDD * sizeof(float), 0);
    cudaMemsetAsync(p_cs, 0, (size_t)NN * 3 * sizeof(float), 0);
    cudaMemsetAsync(p_cnt, 0, (size_t)NN * sizeof(float), 0);

    cudaFuncSetAttribute(edge_kernel, cudaFuncAttributeMaxDynamicSharedMemorySize, EDGE_SMEM_BYTES);
    cudaFuncSetAttribute(node_kernel, cudaFuncAttributeMaxDynamicSharedMemorySize, NODE_SMEM_BYTES);

    edge_kernel<<<NE / TE, NT, EDGE_SMEM_BYTES>>>(
        h, coord, eattr, ei, We1, be1, We2, be2, Wc1, bc1, Wc2, bc2,
        m_out, (float*)p_agg, (float*)p_cs, (float*)p_cnt);

    node_kernel<<<(NN + 63) / 64, NT, NODE_SMEM_BYTES>>>(
        h, coord, Wn1, bn1, Wn2, bn2,
        (const float*)p_agg, (const float*)p_cs, (const float*)p_cnt,
        h_out, c_out);
}

// round 4
// speedup vs baseline: 2.1960x; 2.1960x over previous
#include <cuda_runtime.h>
#include <cuda_bf16.h>
#include <stdint.h>

#define NN 50000
#define NE 800000

// ---------------- device scratch ----------------
__device__ float g_agg[(size_t)NN * 128];
__device__ float g_cs[NN * 3];
__device__ float g_cnt[NN];
__device__ uint32_t g_hpack[(size_t)NN * 128];       // (lo<<16)|hi split of h
__device__ uint32_t g_W1hi[128 * 144], g_W1lo[128 * 144];  // We1^T pair-packed, K padded 288
__device__ uint32_t g_W2hi[128 * 64],  g_W2lo[128 * 64];   // We2^T
__device__ uint32_t g_W3hi[128 * 64],  g_W3lo[128 * 64];   // Wc1^T

__device__ __forceinline__ unsigned short f2bf(float x) {
    __nv_bfloat16 b = __float2bfloat16(x);
    return *reinterpret_cast<unsigned short*>(&b);
}
__device__ __forceinline__ float bf2f(unsigned short u) {
    __nv_bfloat16 b = *reinterpret_cast<__nv_bfloat16*>(&u);
    return __bfloat162float(b);
}
__device__ __forceinline__ float silu_f(float x) { return x / (1.0f + __expf(-x)); }

__device__ __forceinline__ void red4(float* p, float a, float b, float c, float d) {
    asm volatile("red.global.add.v4.f32 [%0], {%1,%2,%3,%4};"
                 :: "l"(p), "f"(a), "f"(b), "f"(c), "f"(d) : "memory");
}
__device__ __forceinline__ void red1(float* p, float a) {
    asm volatile("red.global.add.f32 [%0], %1;" :: "l"(p), "f"(a) : "memory");
}
__device__ __forceinline__ uint32_t smem_u32(const void* p) {
    uint32_t a;
    asm("{ .reg .u64 t; cvta.to.shared.u64 t, %1; cvt.u32.u64 %0, t; }" : "=r"(a) : "l"(p));
    return a;
}
__device__ __forceinline__ void cp16(uint32_t dst, const void* src) {
    asm volatile("cp.async.ca.shared.global [%0], [%1], 16;" :: "r"(dst), "l"(src));
}

#define MMA(ac, a, b0, b1) \
    asm volatile("mma.sync.aligned.m16n8k16.row.col.f32.bf16.bf16.f32 " \
        "{%0,%1,%2,%3}, {%4,%5,%6,%7}, {%8,%9}, {%0,%1,%2,%3};" \
        : "+f"((ac)[0]), "+f"((ac)[1]), "+f"((ac)[2]), "+f"((ac)[3]) \
        : "r"((a)[0]), "r"((a)[1]), "r"((a)[2]), "r"((a)[3]), "r"(b0), "r"(b1))

// ---------------- smem layout (bytes) ----------------
#define OFF_AHI   0u          // GEMM1 A_hi [128][296] u16 (75776)
#define OFF_ALO   75776u      // GEMM1 A_lo (75776)
#define M2HI      0u          // GEMM2/3 A_hi [128][136] u16 (34816)
#define M2LO      34816u
#define OFF_MS    69632u      // m fp32 stage [128][128] (65536)
#define OFF_B     151552u     // B chunks: 2 buf x (hi 10240 + lo 10240)
#define B_BUF_ST  20480u
#define B_HL_ST   10240u
#define OFF_ROW   192512u     // 128 int
#define OFF_D     193024u     // 3 x 128 f
#define OFF_BIAS  194560u     // 512 f (be1,be2,bc1,Wc2)
#define OFF_WSUM  196608u     // 128 f
#define OFF_BC2   197120u
#define EDGE_SMEM 197376u
#define SA1 296
#define SA2 136

extern __shared__ char dynsmem[];

// ---------------- prep kernels ----------------
__global__ void prep_h_kernel(const float* __restrict__ h) {
    size_t i = (size_t)blockIdx.x * 256 + threadIdx.x;
    if (i < (size_t)NN * 128) {
        float v = h[i];
        unsigned short hi = f2bf(v);
        unsigned short lo = f2bf(v - bf2f(hi));
        g_hpack[i] = (uint32_t)hi | ((uint32_t)lo << 16);
    }
}

__global__ void prep_w_kernel(const float* __restrict__ We1,
                              const float* __restrict__ We2,
                              const float* __restrict__ Wc1) {
    int t = blockIdx.x * 256 + threadIdx.x;
    const float* W; uint32_t *dh, *dl; int n, kp, K;
    if (t < 18432)      { n = t / 144; kp = t % 144; W = We1; dh = g_W1hi + n*144 + kp; dl = g_W1lo + n*144 + kp; K = 273; }
    else if (t < 26624) { int u = t - 18432; n = u >> 6; kp = u & 63; W = We2; dh = g_W2hi + n*64 + kp; dl = g_W2lo + n*64 + kp; K = 128; }
    else if (t < 34816) { int u = t - 26624; n = u >> 6; kp = u & 63; W = Wc1; dh = g_W3hi + n*64 + kp; dl = g_W3lo + n*64 + kp; K = 128; }
    else return;
    int k0 = kp * 2, k1 = k0 + 1;
    float v0 = (k0 < K) ? W[k0 * 128 + n] : 0.0f;
    float v1 = (k1 < K) ? W[k1 * 128 + n] : 0.0f;
    unsigned short h0 = f2bf(v0), h1 = f2bf(v1);
    unsigned short l0 = f2bf(v0 - bf2f(h0)), l1 = f2bf(v1 - bf2f(h1));
    *dh = (uint32_t)h0 | ((uint32_t)h1 << 16);
    *dl = (uint32_t)l0 | ((uint32_t)l1 << 16);
}

// ---------------- edge kernel pieces ----------------
__device__ __forceinline__ void issue_chunk(uint32_t sb, int buf,
                                            const uint32_t* gHi, const uint32_t* gLo,
                                            int kb, int Kw) {
    int tid = threadIdx.x;
    #pragma unroll
    for (int j = 0; j < 4; j++) {
        int g = tid + 256 * j;
        int arr = g >> 9;
        int n = (g >> 2) & 127;
        int q = g & 3;
        const uint32_t* src = (arr ? gLo : gHi) + n * Kw + (kb >> 1) + q * 4;
        uint32_t dst = sb + OFF_B + (uint32_t)buf * B_BUF_ST + (uint32_t)arr * B_HL_ST
                     + (uint32_t)(n * 20 + q * 4) * 4u;
        cp16(dst, src);
    }
    asm volatile("cp.async.commit_group;" ::: "memory");
}

__device__ __forceinline__ void mma_step(const uint16_t* sAh, const uint16_t* sAl, int SA,
                                         int kb, const uint32_t* bh32, const uint32_t* bl32,
                                         int kloc, int warpM, int warpN, int gr, int ci,
                                         float acc[2][8][4]) {
    uint32_t ah[2][4], al[2][4];
    #pragma unroll
    for (int mt = 0; mt < 2; mt++) {
        int rb = warpM * 32 + mt * 16 + gr;
        const uint16_t* p = sAh + rb * SA + kb + ci * 2;
        ah[mt][0] = *(const uint32_t*)p;
        ah[mt][1] = *(const uint32_t*)(p + 8 * SA);
        ah[mt][2] = *(const uint32_t*)(p + 8);
        ah[mt][3] = *(const uint32_t*)(p + 8 * SA + 8);
        const uint16_t* q = sAl + rb * SA + kb + ci * 2;
        al[mt][0] = *(const uint32_t*)q;
        al[mt][1] = *(const uint32_t*)(q + 8 * SA);
        al[mt][2] = *(const uint32_t*)(q + 8);
        al[mt][3] = *(const uint32_t*)(q + 8 * SA + 8);
    }
    #pragma unroll
    for (int nt = 0; nt < 8; nt++) {
        int n = warpN * 64 + nt * 8 + gr;
        const uint32_t* pb = bh32 + n * 20 + (kloc >> 1) + ci;
        const uint32_t* pl = bl32 + n * 20 + (kloc >> 1) + ci;
        uint32_t bh0 = pb[0], bh1 = pb[4];
        uint32_t bl0 = pl[0], bl1 = pl[4];
        #pragma unroll
        for (int mt = 0; mt < 2; mt++) {
            MMA(acc[mt][nt], ah[mt], bh0, bh1);
            MMA(acc[mt][nt], ah[mt], bl0, bl1);
            MMA(acc[mt][nt], al[mt], bh0, bh1);
        }
    }
}

__device__ __forceinline__ void gemm_pass(char* smem, uint32_t sb,
    const uint16_t* sAh, const uint16_t* sAl, int SA,
    const uint32_t* gHi, const uint32_t* gLo, int Kw, int nchunks,
    int warpM, int warpN, int gr, int ci, float acc[2][8][4]) {
    issue_chunk(sb, 0, gHi, gLo, 0, Kw);
    for (int c = 0; c < nchunks; c++) {
        if (c + 1 < nchunks) {
            issue_chunk(sb, (c + 1) & 1, gHi, gLo, (c + 1) * 32, Kw);
            asm volatile("cp.async.wait_group 1;" ::: "memory");
        } else {
            asm volatile("cp.async.wait_group 0;" ::: "memory");
        }
        __syncthreads();
        const uint32_t* bh32 = (const uint32_t*)(smem + OFF_B + (uint32_t)(c & 1) * B_BUF_ST);
        const uint32_t* bl32 = (const uint32_t*)(smem + OFF_B + (uint32_t)(c & 1) * B_BUF_ST + B_HL_ST);
        mma_step(sAh, sAl, SA, c * 32,      bh32, bl32, 0,  warpM, warpN, gr, ci, acc);
        mma_step(sAh, sAl, SA, c * 32 + 16, bh32, bl32, 16, warpM, warpN, gr, ci, acc);
        __syncthreads();
    }
}

__global__ void __launch_bounds__(256, 1) edge_kernel(
    const float* __restrict__ coord, const float* __restrict__ eattr,
    const int* __restrict__ ei,
    const float* __restrict__ be1, const float* __restrict__ be2,
    const float* __restrict__ bc1, const float* __restrict__ Wc2,
    const float* __restrict__ bc2,
    float* __restrict__ m_out, float* __restrict__ agg,
    float* __restrict__ cs, float* __restrict__ cnt)
{
    char* smem = dynsmem;
    const uint32_t sb = smem_u32(smem);
    const int tid  = threadIdx.x;
    const int lane = tid & 31;
    const int wid  = tid >> 5;
    const int warpM = wid & 3, warpN = wid >> 2;
    const int gr = lane >> 2, ci = lane & 3;
    const int eb = blockIdx.x * 128;

    uint16_t* sAh = (uint16_t*)(smem + OFF_AHI);
    uint16_t* sAl = (uint16_t*)(smem + OFF_ALO);
    uint16_t* m2h = (uint16_t*)(smem + M2HI);
    uint16_t* m2l = (uint16_t*)(smem + M2LO);
    float* ms     = (float*)(smem + OFF_MS);
    int* s_row    = (int*)(smem + OFF_ROW);
    float* s_dx   = (float*)(smem + OFF_D);
    float* s_dy   = s_dx + 128;
    float* s_dz   = s_dx + 256;
    float* sbias  = (float*)(smem + OFF_BIAS);
    float* s_wsum = (float*)(smem + OFF_WSUM);

    if (tid < 128) {
        sbias[tid] = be1[tid];
        sbias[128 + tid] = be2[tid];
        sbias[256 + tid] = bc1[tid];
        sbias[384 + tid] = Wc2[tid];
        s_wsum[tid] = 0.0f;
    }
    if (tid == 0) *(float*)(smem + OFF_BC2) = bc2[0];

    // per-edge basics
    if (tid < 128) {
        int g = eb + tid;
        int r = ei[g], c = ei[NE + g];
        s_row[tid] = r;
        float dx = coord[r * 3 + 0] - coord[c * 3 + 0];
        float dy = coord[r * 3 + 1] - coord[c * 3 + 1];
        float dz = coord[r * 3 + 2] - coord[c * 3 + 2];
        s_dx[tid] = dx; s_dy[tid] = dy; s_dz[tid] = dz;
        float rad = dx * dx + dy * dy + dz * dz;
        unsigned short hi = f2bf(rad);
        sAh[tid * SA1 + 256] = hi;
        sAl[tid * SA1 + 256] = f2bf(rad - bf2f(hi));
        const float* ea = eattr + (size_t)g * 16;
        #pragma unroll
        for (int j = 0; j < 16; j++) {
            float v = ea[j];
            unsigned short h2 = f2bf(v);
            sAh[tid * SA1 + 257 + j] = h2;
            sAl[tid * SA1 + 257 + j] = f2bf(v - bf2f(h2));
        }
        #pragma unroll
        for (int k = 273; k < 288; k++) { sAh[tid * SA1 + k] = 0; sAl[tid * SA1 + k] = 0; }
    }
    // h gather: 2 threads/edge
    {
        int e = tid >> 1, half = tid & 1;
        int node = ei[half * NE + eb + e];
        const uint4* hp = (const uint4*)(g_hpack + (size_t)node * 128);
        #pragma unroll 4
        for (int j0 = 0; j0 < 128; j0 += 8) {
            uint4 v0 = hp[j0 >> 2];
            uint4 v1 = hp[(j0 >> 2) + 1];
            uint4 h4, l4;
            h4.x = (v0.x & 0xFFFFu) | (v0.y << 16);  l4.x = (v0.x >> 16) | (v0.y & 0xFFFF0000u);
            h4.y = (v0.z & 0xFFFFu) | (v0.w << 16);  l4.y = (v0.z >> 16) | (v0.w & 0xFFFF0000u);
            h4.z = (v1.x & 0xFFFFu) | (v1.y << 16);  l4.z = (v1.x >> 16) | (v1.y & 0xFFFF0000u);
            h4.w = (v1.z & 0xFFFFu) | (v1.w << 16);  l4.w = (v1.z >> 16) | (v1.w & 0xFFFF0000u);
            int o = e * SA1 + half * 128 + j0;
            *(uint4*)(sAh + o) = h4;
            *(uint4*)(sAl + o) = l4;
        }
    }
    __syncthreads();

    float acc[2][8][4];
    #pragma unroll
    for (int a = 0; a < 2; a++)
        #pragma unroll
        for (int b = 0; b < 8; b++)
            #pragma unroll
            for (int d = 0; d < 4; d++) acc[a][b][d] = 0.0f;

    // ---- GEMM1 ----
    gemm_pass(smem, sb, sAh, sAl, SA1, g_W1hi, g_W1lo, 144, 9, warpM, warpN, gr, ci, acc);

    // epilogue 1 -> m1 split (stride 136)
    #pragma unroll
    for (int mt = 0; mt < 2; mt++) {
        int r0 = warpM * 32 + mt * 16 + gr;
        #pragma unroll
        for (int nt = 0; nt < 8; nt++) {
            int c = warpN * 64 + nt * 8 + ci * 2;
            float b0 = sbias[c], b1 = sbias[c + 1];
            float x0 = silu_f(acc[mt][nt][0] + b0), x1 = silu_f(acc[mt][nt][1] + b1);
            float x2 = silu_f(acc[mt][nt][2] + b0), x3 = silu_f(acc[mt][nt][3] + b1);
            unsigned short h0 = f2bf(x0), h1 = f2bf(x1), h2 = f2bf(x2), h3 = f2bf(x3);
            *(uint32_t*)(m2h + r0 * SA2 + c) = (uint32_t)h0 | ((uint32_t)h1 << 16);
            *(uint32_t*)(m2l + r0 * SA2 + c) =
                (uint32_t)f2bf(x0 - bf2f(h0)) | ((uint32_t)f2bf(x1 - bf2f(h1)) << 16);
            *(uint32_t*)(m2h + (r0 + 8) * SA2 + c) = (uint32_t)h2 | ((uint32_t)h3 << 16);
            *(uint32_t*)(m2l + (r0 + 8) * SA2 + c) =
                (uint32_t)f2bf(x2 - bf2f(h2)) | ((uint32_t)f2bf(x3 - bf2f(h3)) << 16);
            acc[mt][nt][0] = acc[mt][nt][1] = acc[mt][nt][2] = acc[mt][nt][3] = 0.0f;
        }
    }
    __syncthreads();

    // ---- GEMM2 ----
    gemm_pass(smem, sb, m2h, m2l, SA2, g_W2hi, g_W2lo, 64, 4, warpM, warpN, gr, ci, acc);

    // epilogue 2 -> m split in place + fp32 stage
    #pragma unroll
    for (int mt = 0; mt < 2; mt++) {
        int r0 = warpM * 32 + mt * 16 + gr;
        #pragma unroll
        for (int nt = 0; nt < 8; nt++) {
            int c = warpN * 64 + nt * 8 + ci * 2;
            float b0 = sbias[128 + c], b1 = sbias[128 + c + 1];
            float x0 = silu_f(acc[mt][nt][0] + b0), x1 = silu_f(acc[mt][nt][1] + b1);
            float x2 = silu_f(acc[mt][nt][2] + b0), x3 = silu_f(acc[mt][nt][3] + b1);
            ms[r0 * 128 + c] = x0; ms[r0 * 128 + c + 1] = x1;
            ms[(r0 + 8) * 128 + c] = x2; ms[(r0 + 8) * 128 + c + 1] = x3;
            unsigned short h0 = f2bf(x0), h1 = f2bf(x1), h2 = f2bf(x2), h3 = f2bf(x3);
            *(uint32_t*)(m2h + r0 * SA2 + c) = (uint32_t)h0 | ((uint32_t)h1 << 16);
            *(uint32_t*)(m2l + r0 * SA2 + c) =
                (uint32_t)f2bf(x0 - bf2f(h0)) | ((uint32_t)f2bf(x1 - bf2f(h1)) << 16);
            *(uint32_t*)(m2h + (r0 + 8) * SA2 + c) = (uint32_t)h2 | ((uint32_t)h3 << 16);
            *(uint32_t*)(m2l + (r0 + 8) * SA2 + c) =
                (uint32_t)f2bf(x2 - bf2f(h2)) | ((uint32_t)f2bf(x3 - bf2f(h3)) << 16);
            acc[mt][nt][0] = acc[mt][nt][1] = acc[mt][nt][2] = acc[mt][nt][3] = 0.0f;
        }
    }
    __syncthreads();

    // ---- GEMM3 ----
    gemm_pass(smem, sb, m2h, m2l, SA2, g_W3hi, g_W3lo, 64, 4, warpM, warpN, gr, ci, acc);

    // scatter m + agg (fp32 stage still valid)
    for (int idx = tid; idx < 128 * 32; idx += 256) {
        int e = idx >> 5, q = (idx & 31) * 4;
        float4 v = *(float4*)(ms + e * 128 + q);
        *(float4*)(m_out + (size_t)(eb + e) * 128 + q) = v;
        red4(agg + (size_t)s_row[e] * 128 + q, v.x, v.y, v.z, v.w);
    }

    // epilogue 3: per-edge coord weight
    {
        float part[2][2] = {{0.f, 0.f}, {0.f, 0.f}};
        #pragma unroll
        for (int mt = 0; mt < 2; mt++)
            #pragma unroll
            for (int nt = 0; nt < 8; nt++) {
                int c = warpN * 64 + nt * 8 + ci * 2;
                float b0 = sbias[256 + c], b1 = sbias[256 + c + 1];
                float w0 = sbias[384 + c], w1 = sbias[384 + c + 1];
                part[mt][0] += silu_f(acc[mt][nt][0] + b0) * w0 + silu_f(acc[mt][nt][1] + b1) * w1;
                part[mt][1] += silu_f(acc[mt][nt][2] + b0) * w0 + silu_f(acc[mt][nt][3] + b1) * w1;
            }
        #pragma unroll
        for (int off = 1; off <= 2; off <<= 1) {
            #pragma unroll
            for (int mt = 0; mt < 2; mt++) {
                part[mt][0] += __shfl_xor_sync(0xFFFFFFFFu, part[mt][0], off);
                part[mt][1] += __shfl_xor_sync(0xFFFFFFFFu, part[mt][1], off);
            }
        }
        if (ci == 0) {
            #pragma unroll
            for (int mt = 0; mt < 2; mt++) {
                int r0 = warpM * 32 + mt * 16 + gr;
                atomicAdd(&s_wsum[r0], part[mt][0]);
                atomicAdd(&s_wsum[r0 + 8], part[mt][1]);
            }
        }
    }
    __syncthreads();

    if (tid < 128) {
        float w = s_wsum[tid] + *(float*)(smem + OFF_BC2);
        int r = s_row[tid];
        red1(cs + r * 3 + 0, s_dx[tid] * w);
        red1(cs + r * 3 + 1, s_dy[tid] * w);
        red1(cs + r * 3 + 2, s_dz[tid] * w);
        red1(cnt + r, 1.0f);
    }
}

// ---------------- node kernel (fp32) ----------------
#define NODE_SMEM_BYTES (27136 * 4)
__global__ void __launch_bounds__(256, 1) node_kernel(
    const float* __restrict__ h, const float* __restrict__ coord,
    const float* __restrict__ Wn1, const float* __restrict__ bn1,
    const float* __restrict__ Wn2, const float* __restrict__ bn2,
    const float* __restrict__ agg, const float* __restrict__ cs,
    const float* __restrict__ cnt,
    float* __restrict__ h_out, float* __restrict__ c_out)
{
    float* smem_f = (float*)dynsmem;
    float* s_nin = smem_f;
    float* s_w   = smem_f + 16640;
    float* s_h1  = smem_f + 18688;
    const int tid = threadIdx.x;
    const int nb = blockIdx.x * 64;
    const int lane = tid & 31;
    const int warp = tid >> 5;
    const int ebase = warp * 8;

    for (int idx = tid; idx < 64 * 64; idx += 256) {
        int n = idx >> 6, f = idx & 63;
        int node = nb + n;
        float4 v = make_float4(0.f, 0.f, 0.f, 0.f);
        if (node < NN) {
            if (f < 32) v = *(const float4*)(h + (size_t)node * 128 + f * 4);
            else        v = *(const float4*)(agg + (size_t)node * 128 + (f - 32) * 4);
        }
        *(float4*)&s_nin[n * 260 + f * 4] = v;
    }
    __syncthreads();

    float acc[8][4];
    #pragma unroll
    for (int i = 0; i < 8; i++)
        #pragma unroll
        for (int j = 0; j < 4; j++) acc[i][j] = 0.0f;

    for (int kb = 0; kb < 256; kb += 16) {
        for (int idx = tid; idx < 2048; idx += 256) s_w[idx] = Wn1[kb * 128 + idx];
        __syncthreads();
        #pragma unroll
        for (int k = 0; k < 16; k++) {
            float4 b = *(const float4*)&s_w[k * 128 + lane * 4];
            float bv[4] = {b.x, b.y, b.z, b.w};
            float av[8];
            #pragma unroll
            for (int i = 0; i < 8; i++) av[i] = s_nin[(ebase + i) * 260 + kb + k];
            #pragma unroll
            for (int i = 0; i < 8; i++)
                #pragma unroll
                for (int j = 0; j < 4; j++) acc[i][j] = fmaf(av[i], bv[j], acc[i][j]);
        }
        __syncthreads();
    }
    {
        float4 b1 = *(const float4*)&bn1[lane * 4];
        float bv[4] = {b1.x, b1.y, b1.z, b1.w};
        #pragma unroll
        for (int i = 0; i < 8; i++) {
            float4 o;
            o.x = silu_f(acc[i][0] + bv[0]); o.y = silu_f(acc[i][1] + bv[1]);
            o.z = silu_f(acc[i][2] + bv[2]); o.w = silu_f(acc[i][3] + bv[3]);
            *(float4*)&s_h1[(ebase + i) * 132 + lane * 4] = o;
        }
    }
    #pragma unroll
    for (int i = 0; i < 8; i++)
        #pragma unroll
        for (int j = 0; j < 4; j++) acc[i][j] = 0.0f;

    for (int kb = 0; kb < 128; kb += 16) {
        for (int idx = tid; idx < 2048; idx += 256) s_w[idx] = Wn2[kb * 128 + idx];
        __syncthreads();
        #pragma unroll
        for (int k = 0; k < 16; k++) {
            float4 b = *(const float4*)&s_w[k * 128 + lane * 4];
            float bv[4] = {b.x, b.y, b.z, b.w};
            float av[8];
            #pragma unroll
            for (int i = 0; i < 8; i++) av[i] = s_h1[(ebase + i) * 132 + kb + k];
            #pragma unroll
            for (int i = 0; i < 8; i++)
                #pragma unroll
                for (int j = 0; j < 4; j++) acc[i][j] = fmaf(av[i], bv[j], acc[i][j]);
        }
        __syncthreads();
    }
    {
        float4 b2 = *(const float4*)&bn2[lane * 4];
        #pragma unroll
        for (int i = 0; i < 8; i++) {
            int node = nb + ebase + i;
            if (node < NN) {
                float4 o;
                o.x = acc[i][0] + b2.x; o.y = acc[i][1] + b2.y;
                o.z = acc[i][2] + b2.z; o.w = acc[i][3] + b2.w;
                *(float4*)&h_out[(size_t)node * 128 + lane * 4] = o;
            }
        }
    }
    if (tid < 64) {
        int node = nb + tid;
        if (node < NN) {
            float dn = fmaxf(cnt[node], 1.0f);
            #pragma unroll
            for (int d = 0; d < 3; d++)
                c_out[node * 3 + d] = coord[node * 3 + d] + cs[node * 3 + d] / dn;
        }
    }
}

extern "C" void kernel_launch(void* const* d_in, const int* in_sizes, int n_in,
                              void* d_out, int out_size)
{
    const float* h     = (const float*)d_in[0];
    const float* coord = (const float*)d_in[1];
    const float* eattr = (const float*)d_in[2];
    const int*   ei    = (const int*)d_in[3];
    const float* We1 = (const float*)d_in[4];
    const float* be1 = (const float*)d_in[5];
    const float* We2 = (const float*)d_in[6];
    const float* be2 = (const float*)d_in[7];
    const float* Wn1 = (const float*)d_in[8];
    const float* bn1 = (const float*)d_in[9];
    const float* Wn2 = (const float*)d_in[10];
    const float* bn2 = (const float*)d_in[11];
    const float* Wc1 = (const float*)d_in[12];
    const float* bc1 = (const float*)d_in[13];
    const float* Wc2 = (const float*)d_in[14];
    const float* bc2 = (const float*)d_in[15];

    float* out   = (float*)d_out;
    float* h_out = out;
    float* c_out = out + (size_t)NN * 128;
    float* m_out = c_out + (size_t)NN * 3;

    void *p_agg, *p_cs, *p_cnt;
    cudaGetSymbolAddress(&p_agg, g_agg);
    cudaGetSymbolAddress(&p_cs, g_cs);
    cudaGetSymbolAddress(&p_cnt, g_cnt);
    cudaMemsetAsync(p_agg, 0, (size_t)NN * 128 * sizeof(float), 0);
    cudaMemsetAsync(p_cs, 0, (size_t)NN * 3 * sizeof(float), 0);
    cudaMemsetAsync(p_cnt, 0, (size_t)NN * sizeof(float), 0);

    prep_h_kernel<<<(NN * 128 + 255) / 256, 256>>>(h);
    prep_w_kernel<<<136, 256>>>(We1, We2, Wc1);

    cudaFuncSetAttribute(edge_kernel, cudaFuncAttributeMaxDynamicSharedMemorySize, EDGE_SMEM);
    cudaFuncSetAttribute(node_kernel, cudaFuncAttributeMaxDynamicSharedMemorySize, NODE_SMEM_BYTES);

    edge_kernel<<<NE / 128, 256, EDGE_SMEM>>>(
        coord, eattr, ei, be1, be2, bc1, Wc2, bc2,
        m_out, (float*)p_agg, (float*)p_cs, (float*)p_cnt);

    node_kernel<<<(NN + 63) / 64, 256, NODE_SMEM_BYTES>>>(
        h, coord, Wn1, bn1, Wn2, bn2,
        (const float*)p_agg, (const float*)p_cs, (const float*)p_cnt,
        h_out, c_out);
}

// round 5
// speedup vs baseline: 3.1297x; 1.4252x over previous
#include <cuda_runtime.h>
#include <cuda_bf16.h>
#include <stdint.h>

#define NN 50000
#define NE 800000

// ---------------- device scratch ----------------
__device__ float g_agg[(size_t)NN * 128];
__device__ float g_cs[NN * 3];
__device__ float g_cnt[NN];
__device__ float g_H1a[(size_t)NN * 128];
__device__ float g_H1b[(size_t)NN * 128];
__device__ uint32_t g_hpack[(size_t)NN * 128];   // (lo<<16)|hi split of h
__device__ uint32_t g_W1ahi[128 * 64], g_W1alo[128 * 64];
__device__ uint32_t g_W1bhi[128 * 64], g_W1blo[128 * 64];
__device__ uint32_t g_W2hi[128 * 64],  g_W2lo[128 * 64];
__device__ uint32_t g_W3hi[128 * 64],  g_W3lo[128 * 64];

__device__ __forceinline__ unsigned short f2bf(float x) {
    __nv_bfloat16 b = __float2bfloat16(x);
    return *reinterpret_cast<unsigned short*>(&b);
}
__device__ __forceinline__ float bf2f(unsigned short u) {
    __nv_bfloat16 b = *reinterpret_cast<__nv_bfloat16*>(&u);
    return __bfloat162float(b);
}
__device__ __forceinline__ float silu_f(float x) { return x / (1.0f + __expf(-x)); }
__device__ __forceinline__ void red2(float* p, float a, float b) {
    asm volatile("red.global.add.v2.f32 [%0], {%1,%2};" :: "l"(p), "f"(a), "f"(b) : "memory");
}
__device__ __forceinline__ void red1(float* p, float a) {
    asm volatile("red.global.add.f32 [%0], %1;" :: "l"(p), "f"(a) : "memory");
}
__device__ __forceinline__ uint32_t smem_u32(const void* p) {
    uint32_t a;
    asm("{ .reg .u64 t; cvta.to.shared.u64 t, %1; cvt.u32.u64 %0, t; }" : "=r"(a) : "l"(p));
    return a;
}
__device__ __forceinline__ void cp16(uint32_t dst, const void* src) {
    asm volatile("cp.async.ca.shared.global [%0], [%1], 16;" :: "r"(dst), "l"(src));
}
#define MMA(ac, a, b0, b1) \
    asm volatile("mma.sync.aligned.m16n8k16.row.col.f32.bf16.bf16.f32 " \
        "{%0,%1,%2,%3}, {%4,%5,%6,%7}, {%8,%9}, {%0,%1,%2,%3};" \
        : "+f"((ac)[0]), "+f"((ac)[1]), "+f"((ac)[2]), "+f"((ac)[3]) \
        : "r"((a)[0]), "r"((a)[1]), "r"((a)[2]), "r"((a)[3]), "r"(b0), "r"(b1))

#define SA2 136
// edge smem layout (bytes)
#define M2HI      0u
#define M2LO      34816u
#define OFF_B     69632u      // single B chunk buffer: hi 10240 + lo 10240
#define B_HL_ST   10240u
#define OFF_W1C   90112u      // [17][128] fp32
#define OFF_BIAS  98816u      // 512 f: be1,be2,bc1,Wc2
#define OFF_ROW   100864u
#define OFF_COL   101376u
#define OFF_D     101888u     // 3 x 128 f
#define OFF_RAD   103424u
#define OFF_WSUM  103936u
#define OFF_BC2   104448u
#define EDGE_SMEM 104480u
// h1 smem layout
#define H1_AH     0u
#define H1_AL     34816u
#define H1_B      69632u
#define H1_SMEM   90112u

extern __shared__ char dynsmem[];

// ---------------- prep ----------------
__global__ void prep_h_kernel(const float* __restrict__ h) {
    size_t i = (size_t)blockIdx.x * 256 + threadIdx.x;
    if (i < (size_t)NN * 128) {
        float v = h[i];
        unsigned short hi = f2bf(v);
        unsigned short lo = f2bf(v - bf2f(hi));
        g_hpack[i] = (uint32_t)hi | ((uint32_t)lo << 16);
    }
}
__global__ void prep_w_kernel(const float* __restrict__ We1,
                              const float* __restrict__ We2,
                              const float* __restrict__ Wc1) {
    int t = blockIdx.x * 256 + threadIdx.x;
    if (t >= 32768) return;
    int img = t >> 13, u = t & 8191, n = u >> 6, kp = u & 63;
    int k0 = kp * 2, k1 = k0 + 1;
    float v0, v1; uint32_t *dh, *dl;
    if (img == 0)      { v0 = We1[k0 * 128 + n];        v1 = We1[k1 * 128 + n];
                         dh = g_W1ahi; dl = g_W1alo; }
    else if (img == 1) { v0 = We1[(128 + k0) * 128 + n]; v1 = We1[(128 + k1) * 128 + n];
                         dh = g_W1bhi; dl = g_W1blo; }
    else if (img == 2) { v0 = We2[k0 * 128 + n];        v1 = We2[k1 * 128 + n];
                         dh = g_W2hi; dl = g_W2lo; }
    else               { v0 = Wc1[k0 * 128 + n];        v1 = Wc1[k1 * 128 + n];
                         dh = g_W3hi; dl = g_W3lo; }
    unsigned short h0 = f2bf(v0), h1 = f2bf(v1);
    *(dh + n * 64 + kp) = (uint32_t)h0 | ((uint32_t)h1 << 16);
    *(dl + n * 64 + kp) = (uint32_t)f2bf(v0 - bf2f(h0)) | ((uint32_t)f2bf(v1 - bf2f(h1)) << 16);
}

// ---------------- shared GEMM machinery ----------------
__device__ __forceinline__ void issue_chunk(uint32_t sb, uint32_t offB,
                                            const uint32_t* gHi, const uint32_t* gLo, int kb) {
    int tid = threadIdx.x;
    #pragma unroll
    for (int j = 0; j < 4; j++) {
        int g = tid + 256 * j;
        int arr = g >> 9;
        int n = (g >> 2) & 127;
        int q = g & 3;
        const uint32_t* src = (arr ? gLo : gHi) + n * 64 + (kb >> 1) + q * 4;
        uint32_t dst = sb + offB + (uint32_t)arr * B_HL_ST + (uint32_t)(n * 20 + q * 4) * 4u;
        cp16(dst, src);
    }
    asm volatile("cp.async.commit_group;" ::: "memory");
}

__device__ __forceinline__ void mma_step(const uint16_t* sAh, const uint16_t* sAl,
                                         int kb, const uint32_t* bh32, const uint32_t* bl32,
                                         int kloc, int warpM, int warpN, int gr, int ci,
                                         float acc[2][8][4]) {
    uint32_t ah[2][4], al[2][4];
    #pragma unroll
    for (int mt = 0; mt < 2; mt++) {
        int rb = warpM * 32 + mt * 16 + gr;
        const uint16_t* p = sAh + rb * SA2 + kb + ci * 2;
        ah[mt][0] = *(const uint32_t*)p;
        ah[mt][1] = *(const uint32_t*)(p + 8 * SA2);
        ah[mt][2] = *(const uint32_t*)(p + 8);
        ah[mt][3] = *(const uint32_t*)(p + 8 * SA2 + 8);
        const uint16_t* q = sAl + rb * SA2 + kb + ci * 2;
        al[mt][0] = *(const uint32_t*)q;
        al[mt][1] = *(const uint32_t*)(q + 8 * SA2);
        al[mt][2] = *(const uint32_t*)(q + 8);
        al[mt][3] = *(const uint32_t*)(q + 8 * SA2 + 8);
    }
    #pragma unroll
    for (int nt = 0; nt < 8; nt++) {
        int n = warpN * 64 + nt * 8 + gr;
        const uint32_t* pb = bh32 + n * 20 + (kloc >> 1) + ci;
        const uint32_t* pl = bl32 + n * 20 + (kloc >> 1) + ci;
        uint32_t bh0 = pb[0], bh1 = pb[4];
        uint32_t bl0 = pl[0], bl1 = pl[4];
        #pragma unroll
        for (int mt = 0; mt < 2; mt++) {
            MMA(acc[mt][nt], ah[mt], bh0, bh1);
            MMA(acc[mt][nt], ah[mt], bl0, bl1);
            MMA(acc[mt][nt], al[mt], bh0, bh1);
        }
    }
}

// single-buffered K=128 pass (4 chunks of K32)
__device__ __forceinline__ void gemm128(char* smem, uint32_t sb, uint32_t offA_h,
    uint32_t offA_l, uint32_t offB, const uint32_t* gHi, const uint32_t* gLo,
    int warpM, int warpN, int gr, int ci, float acc[2][8][4]) {
    const uint16_t* sAh = (const uint16_t*)(smem + offA_h);
    const uint16_t* sAl = (const uint16_t*)(smem + offA_l);
    const uint32_t* bh32 = (const uint32_t*)(smem + offB);
    const uint32_t* bl32 = (const uint32_t*)(smem + offB + B_HL_ST);
    for (int c = 0; c < 4; c++) {
        issue_chunk(sb, offB, gHi, gLo, c * 32);
        asm volatile("cp.async.wait_group 0;" ::: "memory");
        __syncthreads();
        mma_step(sAh, sAl, c * 32,      bh32, bl32, 0,  warpM, warpN, gr, ci, acc);
        mma_step(sAh, sAl, c * 32 + 16, bh32, bl32, 16, warpM, warpN, gr, ci, acc);
        __syncthreads();
    }
}

// ---------------- H1 precompute kernel ----------------
__global__ void __launch_bounds__(256, 2) h1_kernel() {
    char* smem = dynsmem;
    const uint32_t sb = smem_u32(smem);
    const int tid = threadIdx.x;
    const int lane = tid & 31, wid = tid >> 5;
    const int warpM = wid & 3, warpN = wid >> 2;
    const int gr = lane >> 2, ci = lane & 3;
    const int nb = blockIdx.x * 128;

    uint16_t* aH = (uint16_t*)(smem + H1_AH);
    uint16_t* aL = (uint16_t*)(smem + H1_AL);
    {   // build A = h split (2 threads per node, 64 feats each)
        int e = tid >> 1, half = tid & 1;
        int node = nb + e; if (node >= NN) node = NN - 1;
        const uint4* hp = (const uint4*)(g_hpack + (size_t)node * 128 + half * 64);
        #pragma unroll 4
        for (int j0 = 0; j0 < 64; j0 += 8) {
            uint4 v0 = hp[j0 >> 2], v1 = hp[(j0 >> 2) + 1];
            uint4 h4, l4;
            h4.x = (v0.x & 0xFFFFu) | (v0.y << 16);  l4.x = (v0.x >> 16) | (v0.y & 0xFFFF0000u);
            h4.y = (v0.z & 0xFFFFu) | (v0.w << 16);  l4.y = (v0.z >> 16) | (v0.w & 0xFFFF0000u);
            h4.z = (v1.x & 0xFFFFu) | (v1.y << 16);  l4.z = (v1.x >> 16) | (v1.y & 0xFFFF0000u);
            h4.w = (v1.z & 0xFFFFu) | (v1.w << 16);  l4.w = (v1.z >> 16) | (v1.w & 0xFFFF0000u);
            int o = e * SA2 + half * 64 + j0;
            *(uint4*)(aH + o) = h4;
            *(uint4*)(aL + o) = l4;
        }
    }
    __syncthreads();

    float acc[2][8][4];
    float* Hdst[2] = {g_H1a, g_H1b};
    const uint32_t* WH[2] = {g_W1ahi, g_W1bhi};
    const uint32_t* WL[2] = {g_W1alo, g_W1blo};
    for (int pass = 0; pass < 2; pass++) {
        #pragma unroll
        for (int a = 0; a < 2; a++)
            #pragma unroll
            for (int b = 0; b < 8; b++)
                #pragma unroll
                for (int d = 0; d < 4; d++) acc[a][b][d] = 0.0f;
        gemm128(smem, sb, H1_AH, H1_AL, H1_B, WH[pass], WL[pass],
                warpM, warpN, gr, ci, acc);
        float* H = Hdst[pass];
        #pragma unroll
        for (int mt = 0; mt < 2; mt++) {
            int row = nb + warpM * 32 + mt * 16 + gr;
            #pragma unroll
            for (int nt = 0; nt < 8; nt++) {
                int c = warpN * 64 + nt * 8 + ci * 2;
                if (row < NN)
                    *(float2*)(H + (size_t)row * 128 + c) =
                        make_float2(acc[mt][nt][0], acc[mt][nt][1]);
                if (row + 8 < NN)
                    *(float2*)(H + (size_t)(row + 8) * 128 + c) =
                        make_float2(acc[mt][nt][2], acc[mt][nt][3]);
            }
        }
        __syncthreads();
    }
}

// ---------------- edge kernel ----------------
__global__ void __launch_bounds__(256, 2) edge_kernel(
    const float* __restrict__ coord, const float* __restrict__ eattr,
    const int* __restrict__ ei, const float* __restrict__ We1,
    const float* __restrict__ be1, const float* __restrict__ be2,
    const float* __restrict__ bc1, const float* __restrict__ Wc2,
    const float* __restrict__ bc2,
    float* __restrict__ m_out, float* __restrict__ agg,
    float* __restrict__ cs, float* __restrict__ cnt)
{
    char* smem = dynsmem;
    const uint32_t sb = smem_u32(smem);
    const int tid = threadIdx.x;
    const int lane = tid & 31, wid = tid >> 5;
    const int warpM = wid & 3, warpN = wid >> 2;
    const int gr = lane >> 2, ci = lane & 3;
    const int eb = blockIdx.x * 128;

    uint16_t* m2h = (uint16_t*)(smem + M2HI);
    uint16_t* m2l = (uint16_t*)(smem + M2LO);
    float* w1c    = (float*)(smem + OFF_W1C);
    float* sbias  = (float*)(smem + OFF_BIAS);
    int* s_row    = (int*)(smem + OFF_ROW);
    int* s_col    = (int*)(smem + OFF_COL);
    float* s_dx   = (float*)(smem + OFF_D);
    float* s_dy   = s_dx + 128;
    float* s_dz   = s_dx + 256;
    float* s_rad  = (float*)(smem + OFF_RAD);
    float* s_wsum = (float*)(smem + OFF_WSUM);

    // stage We1c rows 256..272 ([17][128]) + biases
    for (int i = tid; i < 17 * 128; i += 256) w1c[i] = We1[256 * 128 + i];
    if (tid < 128) {
        sbias[tid] = be1[tid]; sbias[128 + tid] = be2[tid];
        sbias[256 + tid] = bc1[tid]; sbias[384 + tid] = Wc2[tid];
        s_wsum[tid] = 0.0f;
    }
    if (tid == 0) *(float*)(smem + OFF_BC2) = bc2[0];
    if (tid < 128) {
        int g = eb + tid;
        int r = ei[g], c = ei[NE + g];
        s_row[tid] = r; s_col[tid] = c;
        float dx = coord[r * 3 + 0] - coord[c * 3 + 0];
        float dy = coord[r * 3 + 1] - coord[c * 3 + 1];
        float dz = coord[r * 3 + 2] - coord[c * 3 + 2];
        s_dx[tid] = dx; s_dy[tid] = dy; s_dz[tid] = dz;
        s_rad[tid] = dx * dx + dy * dy + dz * dz;
    }
    __syncthreads();

    // pre phase: m1 = silu(H1a[row] + H1b[col] + be1 + [rad|eattr]@We1c) -> split
    {
        int e = tid >> 1, half = tid & 1;
        int r = s_row[e], c = s_col[e];
        float x[17];
        x[0] = s_rad[e];
        const float* ea = eattr + (size_t)(eb + e) * 16;
        #pragma unroll
        for (int j = 0; j < 16; j++) x[j + 1] = ea[j];
        const float4* pa = (const float4*)(g_H1a + (size_t)r * 128 + half * 64);
        const float4* pb = (const float4*)(g_H1b + (size_t)c * 128 + half * 64);
        #pragma unroll
        for (int cb = 0; cb < 4; cb++) {
            int cc0 = half * 64 + cb * 16;
            float pre[16];
            #pragma unroll
            for (int i = 0; i < 4; i++) {
                float4 va = pa[cb * 4 + i], vb = pb[cb * 4 + i];
                pre[i * 4 + 0] = va.x + vb.x + sbias[cc0 + i * 4 + 0];
                pre[i * 4 + 1] = va.y + vb.y + sbias[cc0 + i * 4 + 1];
                pre[i * 4 + 2] = va.z + vb.z + sbias[cc0 + i * 4 + 2];
                pre[i * 4 + 3] = va.w + vb.w + sbias[cc0 + i * 4 + 3];
            }
            #pragma unroll
            for (int j = 0; j < 17; j++) {
                float xj = x[j];
                #pragma unroll
                for (int i = 0; i < 16; i++)
                    pre[i] = fmaf(xj, w1c[j * 128 + cc0 + i], pre[i]);
            }
            #pragma unroll
            for (int i = 0; i < 16; i += 2) {
                float s0 = silu_f(pre[i]), s1 = silu_f(pre[i + 1]);
                unsigned short h0 = f2bf(s0), h1 = f2bf(s1);
                *(uint32_t*)(m2h + e * SA2 + cc0 + i) = (uint32_t)h0 | ((uint32_t)h1 << 16);
                *(uint32_t*)(m2l + e * SA2 + cc0 + i) =
                    (uint32_t)f2bf(s0 - bf2f(h0)) | ((uint32_t)f2bf(s1 - bf2f(h1)) << 16);
            }
        }
    }
    __syncthreads();

    float acc[2][8][4];
    #pragma unroll
    for (int a = 0; a < 2; a++)
        #pragma unroll
        for (int b = 0; b < 8; b++)
            #pragma unroll
            for (int d = 0; d < 4; d++) acc[a][b][d] = 0.0f;

    // ---- GEMM2: m1 @ We2 ----
    gemm128(smem, sb, M2HI, M2LO, OFF_B, g_W2hi, g_W2lo, warpM, warpN, gr, ci, acc);

    // epilogue 2: m = silu(+be2); write m_out + agg directly; re-split into m2h/m2l
    #pragma unroll
    for (int mt = 0; mt < 2; mt++) {
        int r0 = warpM * 32 + mt * 16 + gr;
        int row0 = s_row[r0], row1 = s_row[r0 + 8];
        #pragma unroll
        for (int nt = 0; nt < 8; nt++) {
            int c = warpN * 64 + nt * 8 + ci * 2;
            float b0 = sbias[128 + c], b1 = sbias[128 + c + 1];
            float x0 = silu_f(acc[mt][nt][0] + b0), x1 = silu_f(acc[mt][nt][1] + b1);
            float x2 = silu_f(acc[mt][nt][2] + b0), x3 = silu_f(acc[mt][nt][3] + b1);
            *(float2*)(m_out + (size_t)(eb + r0) * 128 + c) = make_float2(x0, x1);
            *(float2*)(m_out + (size_t)(eb + r0 + 8) * 128 + c) = make_float2(x2, x3);
            red2(agg + (size_t)row0 * 128 + c, x0, x1);
            red2(agg + (size_t)row1 * 128 + c, x2, x3);
            unsigned short h0 = f2bf(x0), h1 = f2bf(x1), h2 = f2bf(x2), h3 = f2bf(x3);
            *(uint32_t*)(m2h + r0 * SA2 + c) = (uint32_t)h0 | ((uint32_t)h1 << 16);
            *(uint32_t*)(m2l + r0 * SA2 + c) =
                (uint32_t)f2bf(x0 - bf2f(h0)) | ((uint32_t)f2bf(x1 - bf2f(h1)) << 16);
            *(uint32_t*)(m2h + (r0 + 8) * SA2 + c) = (uint32_t)h2 | ((uint32_t)h3 << 16);
            *(uint32_t*)(m2l + (r0 + 8) * SA2 + c) =
                (uint32_t)f2bf(x2 - bf2f(h2)) | ((uint32_t)f2bf(x3 - bf2f(h3)) << 16);
            acc[mt][nt][0] = acc[mt][nt][1] = acc[mt][nt][2] = acc[mt][nt][3] = 0.0f;
        }
    }
    __syncthreads();

    // ---- GEMM3: m @ Wc1 ----
    gemm128(smem, sb, M2HI, M2LO, OFF_B, g_W3hi, g_W3lo, warpM, warpN, gr, ci, acc);

    // epilogue 3: per-edge coord weight
    {
        float part[2][2] = {{0.f, 0.f}, {0.f, 0.f}};
        #pragma unroll
        for (int mt = 0; mt < 2; mt++)
            #pragma unroll
            for (int nt = 0; nt < 8; nt++) {
                int c = warpN * 64 + nt * 8 + ci * 2;
                float b0 = sbias[256 + c], b1 = sbias[256 + c + 1];
                float w0 = sbias[384 + c], w1 = sbias[384 + c + 1];
                part[mt][0] += silu_f(acc[mt][nt][0] + b0) * w0 + silu_f(acc[mt][nt][1] + b1) * w1;
                part[mt][1] += silu_f(acc[mt][nt][2] + b0) * w0 + silu_f(acc[mt][nt][3] + b1) * w1;
            }
        #pragma unroll
        for (int off = 1; off <= 2; off <<= 1) {
            #pragma unroll
            for (int mt = 0; mt < 2; mt++) {
                part[mt][0] += __shfl_xor_sync(0xFFFFFFFFu, part[mt][0], off);
                part[mt][1] += __shfl_xor_sync(0xFFFFFFFFu, part[mt][1], off);
            }
        }
        if (ci == 0) {
            #pragma unroll
            for (int mt = 0; mt < 2; mt++) {
                int r0 = warpM * 32 + mt * 16 + gr;
                atomicAdd(&s_wsum[r0], part[mt][0]);
                atomicAdd(&s_wsum[r0 + 8], part[mt][1]);
            }
        }
    }
    __syncthreads();

    if (tid < 128) {
        float w = s_wsum[tid] + *(float*)(smem + OFF_BC2);
        int r = s_row[tid];
        red1(cs + r * 3 + 0, s_dx[tid] * w);
        red1(cs + r * 3 + 1, s_dy[tid] * w);
        red1(cs + r * 3 + 2, s_dz[tid] * w);
        red1(cnt + r, 1.0f);
    }
}

// ---------------- node kernel (fp32) ----------------
#define NODE_SMEM_BYTES (27136 * 4)
__global__ void __launch_bounds__(256, 1) node_kernel(
    const float* __restrict__ h, const float* __restrict__ coord,
    const float* __restrict__ Wn1, const float* __restrict__ bn1,
    const float* __restrict__ Wn2, const float* __restrict__ bn2,
    const float* __restrict__ agg, const float* __restrict__ cs,
    const float* __restrict__ cnt,
    float* __restrict__ h_out, float* __restrict__ c_out)
{
    float* smem_f = (float*)dynsmem;
    float* s_nin = smem_f;
    float* s_w   = smem_f + 16640;
    float* s_h1  = smem_f + 18688;
    const int tid = threadIdx.x;
    const int nb = blockIdx.x * 64;
    const int lane = tid & 31;
    const int warp = tid >> 5;
    const int ebase = warp * 8;

    for (int idx = tid; idx < 64 * 64; idx += 256) {
        int n = idx >> 6, f = idx & 63;
        int node = nb + n;
        float4 v = make_float4(0.f, 0.f, 0.f, 0.f);
        if (node < NN) {
            if (f < 32) v = *(const float4*)(h + (size_t)node * 128 + f * 4);
            else        v = *(const float4*)(agg + (size_t)node * 128 + (f - 32) * 4);
        }
        *(float4*)&s_nin[n * 260 + f * 4] = v;
    }
    __syncthreads();

    float acc[8][4];
    #pragma unroll
    for (int i = 0; i < 8; i++)
        #pragma unroll
        for (int j = 0; j < 4; j++) acc[i][j] = 0.0f;

    for (int kb = 0; kb < 256; kb += 16) {
        for (int idx = tid; idx < 2048; idx += 256) s_w[idx] = Wn1[kb * 128 + idx];
        __syncthreads();
        #pragma unroll
        for (int k = 0; k < 16; k++) {
            float4 b = *(const float4*)&s_w[k * 128 + lane * 4];
            float bv[4] = {b.x, b.y, b.z, b.w};
            float av[8];
            #pragma unroll
            for (int i = 0; i < 8; i++) av[i] = s_nin[(ebase + i) * 260 + kb + k];
            #pragma unroll
            for (int i = 0; i < 8; i++)
                #pragma unroll
                for (int j = 0; j < 4; j++) acc[i][j] = fmaf(av[i], bv[j], acc[i][j]);
        }
        __syncthreads();
    }
    {
        float4 b1 = *(const float4*)&bn1[lane * 4];
        float bv[4] = {b1.x, b1.y, b1.z, b1.w};
        #pragma unroll
        for (int i = 0; i < 8; i++) {
            float4 o;
            o.x = silu_f(acc[i][0] + bv[0]); o.y = silu_f(acc[i][1] + bv[1]);
            o.z = silu_f(acc[i][2] + bv[2]); o.w = silu_f(acc[i][3] + bv[3]);
            *(float4*)&s_h1[(ebase + i) * 132 + lane * 4] = o;
        }
    }
    #pragma unroll
    for (int i = 0; i < 8; i++)
        #pragma unroll
        for (int j = 0; j < 4; j++) acc[i][j] = 0.0f;

    for (int kb = 0; kb < 128; kb += 16) {
        for (int idx = tid; idx < 2048; idx += 256) s_w[idx] = Wn2[kb * 128 + idx];
        __syncthreads();
        #pragma unroll
        for (int k = 0; k < 16; k++) {
            float4 b = *(const float4*)&s_w[k * 128 + lane * 4];
            float bv[4] = {b.x, b.y, b.z, b.w};
            float av[8];
            #pragma unroll
            for (int i = 0; i < 8; i++) av[i] = s_h1[(ebase + i) * 132 + kb + k];
            #pragma unroll
            for (int i = 0; i < 8; i++)
                #pragma unroll
                for (int j = 0; j < 4; j++) acc[i][j] = fmaf(av[i], bv[j], acc[i][j]);
        }
        __syncthreads();
    }
    {
        float4 b2 = *(const float4*)&bn2[lane * 4];
        #pragma unroll
        for (int i = 0; i < 8; i++) {
            int node = nb + ebase + i;
            if (node < NN) {
                float4 o;
                o.x = acc[i][0] + b2.x; o.y = acc[i][1] + b2.y;
                o.z = acc[i][2] + b2.z; o.w = acc[i][3] + b2.w;
                *(float4*)&h_out[(size_t)node * 128 + lane * 4] = o;
            }
        }
    }
    if (tid < 64) {
        int node = nb + tid;
        if (node < NN) {
            float dn = fmaxf(cnt[node], 1.0f);
            #pragma unroll
            for (int d = 0; d < 3; d++)
                c_out[node * 3 + d] = coord[node * 3 + d] + cs[node * 3 + d] / dn;
        }
    }
}

extern "C" void kernel_launch(void* const* d_in, const int* in_sizes, int n_in,
                              void* d_out, int out_size)
{
    const float* h     = (const float*)d_in[0];
    const float* coord = (const float*)d_in[1];
    const float* eattr = (const float*)d_in[2];
    const int*   ei    = (const int*)d_in[3];
    const float* We1 = (const float*)d_in[4];
    const float* be1 = (const float*)d_in[5];
    const float* We2 = (const float*)d_in[6];
    const float* be2 = (const float*)d_in[7];
    const float* Wn1 = (const float*)d_in[8];
    const float* bn1 = (const float*)d_in[9];
    const float* Wn2 = (const float*)d_in[10];
    const float* bn2 = (const float*)d_in[11];
    const float* Wc1 = (const float*)d_in[12];
    const float* bc1 = (const float*)d_in[13];
    const float* Wc2 = (const float*)d_in[14];
    const float* bc2 = (const float*)d_in[15];

    float* out   = (float*)d_out;
    float* h_out = out;
    float* c_out = out + (size_t)NN * 128;
    float* m_out = c_out + (size_t)NN * 3;

    void *p_agg, *p_cs, *p_cnt;
    cudaGetSymbolAddress(&p_agg, g_agg);
    cudaGetSymbolAddress(&p_cs, g_cs);
    cudaGetSymbolAddress(&p_cnt, g_cnt);
    cudaMemsetAsync(p_agg, 0, (size_t)NN * 128 * sizeof(float), 0);
    cudaMemsetAsync(p_cs, 0, (size_t)NN * 3 * sizeof(float), 0);
    cudaMemsetAsync(p_cnt, 0, (size_t)NN * sizeof(float), 0);

    prep_h_kernel<<<(NN * 128 + 255) / 256, 256>>>(h);
    prep_w_kernel<<<128, 256>>>(We1, We2, Wc1);

    cudaFuncSetAttribute(h1_kernel, cudaFuncAttributeMaxDynamicSharedMemorySize, H1_SMEM);
    cudaFuncSetAttribute(edge_kernel, cudaFuncAttributeMaxDynamicSharedMemorySize, EDGE_SMEM);
    cudaFuncSetAttribute(node_kernel, cudaFuncAttributeMaxDynamicSharedMemorySize, NODE_SMEM_BYTES);

    h1_kernel<<<(NN + 127) / 128, 256, H1_SMEM>>>();

    edge_kernel<<<NE / 128, 256, EDGE_SMEM>>>(
        coord, eattr, ei, We1, be1, be2, bc1, Wc2, bc2,
        m_out, (float*)p_agg, (float*)p_cs, (float*)p_cnt);

    node_kernel<<<(NN + 63) / 64, 256, NODE_SMEM_BYTES>>>(
        h, coord, Wn1, bn1, Wn2, bn2,
        (const float*)p_agg, (const float*)p_cs, (const float*)p_cnt,
        h_out, c_out);
}

// round 6
// speedup vs baseline: 3.2322x; 1.0328x over previous
#include <cuda_runtime.h>
#include <cuda_bf16.h>
#include <stdint.h>

#define NN 50000
#define NE 800000

// ---------------- device scratch ----------------
__device__ float g_agg[(size_t)NN * 128];
__device__ float g_cs4[(size_t)NN * 4];          // {sum dx*w, dy*w, dz*w, cnt}
__device__ float g_H1a[(size_t)NN * 128];
__device__ float g_H1b[(size_t)NN * 128];
__device__ uint32_t g_hpack[(size_t)NN * 128];   // (lo<<16)|hi split of h
__device__ uint32_t g_W1ahi[128 * 64], g_W1alo[128 * 64];
__device__ uint32_t g_W1bhi[128 * 64], g_W1blo[128 * 64];
__device__ uint32_t g_W2hi[128 * 64],  g_W2lo[128 * 64];
__device__ uint32_t g_W3hi[128 * 64],  g_W3lo[128 * 64];

__device__ __forceinline__ unsigned short f2bf(float x) {
    __nv_bfloat16 b = __float2bfloat16(x);
    return *reinterpret_cast<unsigned short*>(&b);
}
__device__ __forceinline__ float bf2f(unsigned short u) {
    __nv_bfloat16 b = *reinterpret_cast<__nv_bfloat16*>(&u);
    return __bfloat162float(b);
}
__device__ __forceinline__ float silu_f(float x) { return x / (1.0f + __expf(-x)); }
__device__ __forceinline__ void red4(float* p, float a, float b, float c, float d) {
    asm volatile("red.global.add.v4.f32 [%0], {%1,%2,%3,%4};"
                 :: "l"(p), "f"(a), "f"(b), "f"(c), "f"(d) : "memory");
}
__device__ __forceinline__ uint32_t smem_u32(const void* p) {
    uint32_t a;
    asm("{ .reg .u64 t; cvta.to.shared.u64 t, %1; cvt.u32.u64 %0, t; }" : "=r"(a) : "l"(p));
    return a;
}
__device__ __forceinline__ void cp16(uint32_t dst, const void* src) {
    asm volatile("cp.async.ca.shared.global [%0], [%1], 16;" :: "r"(dst), "l"(src));
}
__device__ __forceinline__ void ldsm4(uint32_t* r, uint32_t addr) {
    asm volatile("ldmatrix.sync.aligned.m8n8.x4.shared.b16 {%0,%1,%2,%3}, [%4];"
        : "=r"(r[0]), "=r"(r[1]), "=r"(r[2]), "=r"(r[3]) : "r"(addr));
}
#define MMA(ac, a, b0, b1) \
    asm volatile("mma.sync.aligned.m16n8k16.row.col.f32.bf16.bf16.f32 " \
        "{%0,%1,%2,%3}, {%4,%5,%6,%7}, {%8,%9}, {%0,%1,%2,%3};" \
        : "+f"((ac)[0]), "+f"((ac)[1]), "+f"((ac)[2]), "+f"((ac)[3]) \
        : "r"((a)[0]), "r"((a)[1]), "r"((a)[2]), "r"((a)[3]), "r"(b0), "r"(b1))

#define SA2 136
// edge smem layout (bytes)
#define M2HI      0u
#define M2LO      34816u
#define OFF_B     69632u      // single B chunk buffer: hi 10240 + lo 10240
#define B_HL_ST   10240u
#define OFF_W1C   90112u      // [17][128] fp32
#define OFF_BIAS  98816u      // 512 f: be1,be2,bc1,Wc2
#define OFF_ROW   100864u
#define OFF_COL   101376u
#define OFF_D     101888u     // 3 x 128 f
#define OFF_RAD   103424u
#define OFF_WSUM  103936u
#define OFF_BC2   104448u
#define EDGE_SMEM 104480u
// h1 smem layout
#define H1_AH     0u
#define H1_AL     34816u
#define H1_B      69632u
#define H1_SMEM   90112u

extern __shared__ char dynsmem[];

// ---------------- prep ----------------
__global__ void prep_h_kernel(const float* __restrict__ h) {
    size_t i = (size_t)blockIdx.x * 256 + threadIdx.x;
    if (i < (size_t)NN * 128) {
        float v = h[i];
        unsigned short hi = f2bf(v);
        unsigned short lo = f2bf(v - bf2f(hi));
        g_hpack[i] = (uint32_t)hi | ((uint32_t)lo << 16);
    }
}
__global__ void prep_w_kernel(const float* __restrict__ We1,
                              const float* __restrict__ We2,
                              const float* __restrict__ Wc1) {
    int t = blockIdx.x * 256 + threadIdx.x;
    if (t >= 32768) return;
    int img = t >> 13, u = t & 8191, n = u >> 6, kp = u & 63;
    int k0 = kp * 2, k1 = k0 + 1;
    float v0, v1; uint32_t *dh, *dl;
    if (img == 0)      { v0 = We1[k0 * 128 + n];         v1 = We1[k1 * 128 + n];
                         dh = g_W1ahi; dl = g_W1alo; }
    else if (img == 1) { v0 = We1[(128 + k0) * 128 + n]; v1 = We1[(128 + k1) * 128 + n];
                         dh = g_W1bhi; dl = g_W1blo; }
    else if (img == 2) { v0 = We2[k0 * 128 + n];         v1 = We2[k1 * 128 + n];
                         dh = g_W2hi; dl = g_W2lo; }
    else               { v0 = Wc1[k0 * 128 + n];         v1 = Wc1[k1 * 128 + n];
                         dh = g_W3hi; dl = g_W3lo; }
    unsigned short h0 = f2bf(v0), h1 = f2bf(v1);
    *(dh + n * 64 + kp) = (uint32_t)h0 | ((uint32_t)h1 << 16);
    *(dl + n * 64 + kp) = (uint32_t)f2bf(v0 - bf2f(h0)) | ((uint32_t)f2bf(v1 - bf2f(h1)) << 16);
}

// ---------------- shared GEMM machinery ----------------
__device__ __forceinline__ void issue_chunk(uint32_t sb, uint32_t offB,
                                            const uint32_t* gHi, const uint32_t* gLo, int kb) {
    int tid = threadIdx.x;
    #pragma unroll
    for (int j = 0; j < 4; j++) {
        int g = tid + 256 * j;
        int arr = g >> 9;
        int n = (g >> 2) & 127;
        int q = g & 3;
        const uint32_t* src = (arr ? gLo : gHi) + n * 64 + (kb >> 1) + q * 4;
        uint32_t dst = sb + offB + (uint32_t)arr * B_HL_ST + (uint32_t)(n * 20 + q * 4) * 4u;
        cp16(dst, src);
    }
    asm volatile("cp.async.commit_group;" ::: "memory");
}

// ldmatrix-based K16 double-step (does k=kb and k=kb+16 halves via caller)
__device__ __forceinline__ void mma_step(uint32_t aBaseH, uint32_t aBaseL, int kb,
                                         uint32_t bBaseH, uint32_t bBaseL, int kloc,
                                         int warpM, int warpN, int lane,
                                         float acc[2][8][4]) {
    uint32_t ah[2][4], al[2][4];
    const uint32_t arow = (uint32_t)(warpM * 32 + (lane & 15));
    const uint32_t aoff = (uint32_t)(kb + ((lane >> 4) << 3)) * 2u;
    #pragma unroll
    for (int mt = 0; mt < 2; mt++) {
        uint32_t ad = (arow + (uint32_t)(mt * 16)) * (SA2 * 2u) + aoff;
        ldsm4(ah[mt], aBaseH + ad);
        ldsm4(al[mt], aBaseL + ad);
    }
    const uint32_t nrow = (uint32_t)(warpN * 64 + (lane & 7) + ((lane >> 4) << 3));
    const uint32_t boffk = (uint32_t)((kloc >> 1) + ((lane >> 3) & 1) * 4) * 4u;
    #pragma unroll
    for (int p = 0; p < 4; p++) {
        uint32_t bh[4], bl[4];
        uint32_t bd = (nrow + (uint32_t)(p * 16)) * 80u + boffk;
        ldsm4(bh, bBaseH + bd);
        ldsm4(bl, bBaseL + bd);
        int nt0 = p * 2, nt1 = p * 2 + 1;
        #pragma unroll
        for (int mt = 0; mt < 2; mt++) {
            MMA(acc[mt][nt0], ah[mt], bh[0], bh[1]);
            MMA(acc[mt][nt0], ah[mt], bl[0], bl[1]);
            MMA(acc[mt][nt0], al[mt], bh[0], bh[1]);
            MMA(acc[mt][nt1], ah[mt], bh[2], bh[3]);
            MMA(acc[mt][nt1], ah[mt], bl[2], bl[3]);
            MMA(acc[mt][nt1], al[mt], bh[2], bh[3]);
        }
    }
}

// single-buffered K=128 pass (4 chunks of K32)
__device__ __forceinline__ void gemm128(uint32_t sb, uint32_t offA_h, uint32_t offA_l,
    uint32_t offB, const uint32_t* gHi, const uint32_t* gLo,
    int warpM, int warpN, int lane, float acc[2][8][4]) {
    const uint32_t aBaseH = sb + offA_h, aBaseL = sb + offA_l;
    const uint32_t bBaseH = sb + offB, bBaseL = sb + offB + B_HL_ST;
    for (int c = 0; c < 4; c++) {
        issue_chunk(sb, offB, gHi, gLo, c * 32);
        asm volatile("cp.async.wait_group 0;" ::: "memory");
        __syncthreads();
        mma_step(aBaseH, aBaseL, c * 32,      bBaseH, bBaseL, 0,  warpM, warpN, lane, acc);
        mma_step(aBaseH, aBaseL, c * 32 + 16, bBaseH, bBaseL, 16, warpM, warpN, lane, acc);
        __syncthreads();
    }
}

// ---------------- H1 precompute kernel ----------------
__global__ void __launch_bounds__(256, 2) h1_kernel() {
    char* smem = dynsmem;
    const uint32_t sb = smem_u32(smem);
    const int tid = threadIdx.x;
    const int lane = tid & 31, wid = tid >> 5;
    const int warpM = wid & 3, warpN = wid >> 2;
    const int gr = lane >> 2, ci = lane & 3;
    const int nb = blockIdx.x * 128;

    uint16_t* aH = (uint16_t*)(smem + H1_AH);
    uint16_t* aL = (uint16_t*)(smem + H1_AL);
    {
        int e = tid >> 1, half = tid & 1;
        int node = nb + e; if (node >= NN) node = NN - 1;
        const uint4* hp = (const uint4*)(g_hpack + (size_t)node * 128 + half * 64);
        #pragma unroll 4
        for (int j0 = 0; j0 < 64; j0 += 8) {
            uint4 v0 = hp[j0 >> 2], v1 = hp[(j0 >> 2) + 1];
            uint4 h4, l4;
            h4.x = (v0.x & 0xFFFFu) | (v0.y << 16);  l4.x = (v0.x >> 16) | (v0.y & 0xFFFF0000u);
            h4.y = (v0.z & 0xFFFFu) | (v0.w << 16);  l4.y = (v0.z >> 16) | (v0.w & 0xFFFF0000u);
            h4.z = (v1.x & 0xFFFFu) | (v1.y << 16);  l4.z = (v1.x >> 16) | (v1.y & 0xFFFF0000u);
            h4.w = (v1.z & 0xFFFFu) | (v1.w << 16);  l4.w = (v1.z >> 16) | (v1.w & 0xFFFF0000u);
            int o = e * SA2 + half * 64 + j0;
            *(uint4*)(aH + o) = h4;
            *(uint4*)(aL + o) = l4;
        }
    }
    __syncthreads();

    float acc[2][8][4];
    float* Hdst[2] = {g_H1a, g_H1b};
    const uint32_t* WH[2] = {g_W1ahi, g_W1bhi};
    const uint32_t* WL[2] = {g_W1alo, g_W1blo};
    for (int pass = 0; pass < 2; pass++) {
        #pragma unroll
        for (int a = 0; a < 2; a++)
            #pragma unroll
            for (int b = 0; b < 8; b++)
                #pragma unroll
                for (int d = 0; d < 4; d++) acc[a][b][d] = 0.0f;
        gemm128(sb, H1_AH, H1_AL, H1_B, WH[pass], WL[pass], warpM, warpN, lane, acc);
        float* H = Hdst[pass];
        #pragma unroll
        for (int mt = 0; mt < 2; mt++) {
            int row = nb + warpM * 32 + mt * 16 + gr;
            #pragma unroll
            for (int nt = 0; nt < 8; nt++) {
                int c = warpN * 64 + nt * 8 + ci * 2;
                if (row < NN)
                    *(float2*)(H + (size_t)row * 128 + c) =
                        make_float2(acc[mt][nt][0], acc[mt][nt][1]);
                if (row + 8 < NN)
                    *(float2*)(H + (size_t)(row + 8) * 128 + c) =
                        make_float2(acc[mt][nt][2], acc[mt][nt][3]);
            }
        }
        __syncthreads();
    }
}

// ---------------- edge kernel ----------------
__global__ void __launch_bounds__(256, 2) edge_kernel(
    const float* __restrict__ coord, const float* __restrict__ eattr,
    const int* __restrict__ ei, const float* __restrict__ We1,
    const float* __restrict__ be1, const float* __restrict__ be2,
    const float* __restrict__ bc1, const float* __restrict__ Wc2,
    const float* __restrict__ bc2,
    float* __restrict__ m_out, float* __restrict__ agg, float* __restrict__ cs4)
{
    char* smem = dynsmem;
    const uint32_t sb = smem_u32(smem);
    const int tid = threadIdx.x;
    const int lane = tid & 31, wid = tid >> 5;
    const int warpM = wid & 3, warpN = wid >> 2;
    const int gr = lane >> 2, ci = lane & 3;
    const int eb = blockIdx.x * 128;

    uint16_t* m2h = (uint16_t*)(smem + M2HI);
    uint16_t* m2l = (uint16_t*)(smem + M2LO);
    float* w1c    = (float*)(smem + OFF_W1C);
    float* sbias  = (float*)(smem + OFF_BIAS);
    int* s_row    = (int*)(smem + OFF_ROW);
    int* s_col    = (int*)(smem + OFF_COL);
    float* s_dx   = (float*)(smem + OFF_D);
    float* s_dy   = s_dx + 128;
    float* s_dz   = s_dx + 256;
    float* s_rad  = (float*)(smem + OFF_RAD);
    float* s_wsum = (float*)(smem + OFF_WSUM);

    for (int i = tid; i < 17 * 128; i += 256) w1c[i] = We1[256 * 128 + i];
    if (tid < 128) {
        sbias[tid] = be1[tid]; sbias[128 + tid] = be2[tid];
        sbias[256 + tid] = bc1[tid]; sbias[384 + tid] = Wc2[tid];
        s_wsum[tid] = 0.0f;
    }
    if (tid == 0) *(float*)(smem + OFF_BC2) = bc2[0];
    if (tid < 128) {
        int g = eb + tid;
        int r = ei[g], c = ei[NE + g];
        s_row[tid] = r; s_col[tid] = c;
        float dx = coord[r * 3 + 0] - coord[c * 3 + 0];
        float dy = coord[r * 3 + 1] - coord[c * 3 + 1];
        float dz = coord[r * 3 + 2] - coord[c * 3 + 2];
        s_dx[tid] = dx; s_dy[tid] = dy; s_dz[tid] = dz;
        s_rad[tid] = dx * dx + dy * dy + dz * dz;
    }
    __syncthreads();

    // pre phase: m1 = silu(H1a[row] + H1b[col] + be1 + [rad|eattr]@We1c) -> split
    {
        int e = tid >> 1, half = tid & 1;
        int r = s_row[e], c = s_col[e];
        float x[17];
        x[0] = s_rad[e];
        const float* ea = eattr + (size_t)(eb + e) * 16;
        #pragma unroll
        for (int j = 0; j < 16; j++) x[j + 1] = ea[j];
        const float4* pa = (const float4*)(g_H1a + (size_t)r * 128 + half * 64);
        const float4* pb = (const float4*)(g_H1b + (size_t)c * 128 + half * 64);
        #pragma unroll
        for (int cb = 0; cb < 4; cb++) {
            int cc0 = half * 64 + cb * 16;
            float pre[16];
            #pragma unroll
            for (int i = 0; i < 4; i++) {
                float4 va = pa[cb * 4 + i], vb = pb[cb * 4 + i];
                pre[i * 4 + 0] = va.x + vb.x + sbias[cc0 + i * 4 + 0];
                pre[i * 4 + 1] = va.y + vb.y + sbias[cc0 + i * 4 + 1];
                pre[i * 4 + 2] = va.z + vb.z + sbias[cc0 + i * 4 + 2];
                pre[i * 4 + 3] = va.w + vb.w + sbias[cc0 + i * 4 + 3];
            }
            #pragma unroll
            for (int j = 0; j < 17; j++) {
                float xj = x[j];
                #pragma unroll
                for (int i = 0; i < 16; i++)
                    pre[i] = fmaf(xj, w1c[j * 128 + cc0 + i], pre[i]);
            }
            #pragma unroll
            for (int i = 0; i < 16; i += 2) {
                float s0 = silu_f(pre[i]), s1 = silu_f(pre[i + 1]);
                unsigned short h0 = f2bf(s0), h1 = f2bf(s1);
                *(uint32_t*)(m2h + e * SA2 + cc0 + i) = (uint32_t)h0 | ((uint32_t)h1 << 16);
                *(uint32_t*)(m2l + e * SA2 + cc0 + i) =
                    (uint32_t)f2bf(s0 - bf2f(h0)) | ((uint32_t)f2bf(s1 - bf2f(h1)) << 16);
            }
        }
    }
    __syncthreads();

    float acc[2][8][4];
    #pragma unroll
    for (int a = 0; a < 2; a++)
        #pragma unroll
        for (int b = 0; b < 8; b++)
            #pragma unroll
            for (int d = 0; d < 4; d++) acc[a][b][d] = 0.0f;

    // ---- GEMM2: m1 @ We2 ----
    gemm128(sb, M2HI, M2LO, OFF_B, g_W2hi, g_W2lo, warpM, warpN, lane, acc);

    // epilogue 2: m = silu(+be2) -> split back into m2h/m2l (A for GEMM3, and scatter source)
    #pragma unroll
    for (int mt = 0; mt < 2; mt++) {
        int r0 = warpM * 32 + mt * 16 + gr;
        #pragma unroll
        for (int nt = 0; nt < 8; nt++) {
            int c = warpN * 64 + nt * 8 + ci * 2;
            float b0 = sbias[128 + c], b1 = sbias[128 + c + 1];
            float x0 = silu_f(acc[mt][nt][0] + b0), x1 = silu_f(acc[mt][nt][1] + b1);
            float x2 = silu_f(acc[mt][nt][2] + b0), x3 = silu_f(acc[mt][nt][3] + b1);
            unsigned short h0 = f2bf(x0), h1 = f2bf(x1), h2 = f2bf(x2), h3 = f2bf(x3);
            *(uint32_t*)(m2h + r0 * SA2 + c) = (uint32_t)h0 | ((uint32_t)h1 << 16);
            *(uint32_t*)(m2l + r0 * SA2 + c) =
                (uint32_t)f2bf(x0 - bf2f(h0)) | ((uint32_t)f2bf(x1 - bf2f(h1)) << 16);
            *(uint32_t*)(m2h + (r0 + 8) * SA2 + c) = (uint32_t)h2 | ((uint32_t)h3 << 16);
            *(uint32_t*)(m2l + (r0 + 8) * SA2 + c) =
                (uint32_t)f2bf(x2 - bf2f(h2)) | ((uint32_t)f2bf(x3 - bf2f(h3)) << 16);
            acc[mt][nt][0] = acc[mt][nt][1] = acc[mt][nt][2] = acc[mt][nt][3] = 0.0f;
        }
    }
    __syncthreads();

    // ---- GEMM3: m @ Wc1 ----
    gemm128(sb, M2HI, M2LO, OFF_B, g_W3hi, g_W3lo, warpM, warpN, lane, acc);

    // epilogue 3: per-edge coord weight
    {
        float part[2][2] = {{0.f, 0.f}, {0.f, 0.f}};
        #pragma unroll
        for (int mt = 0; mt < 2; mt++)
            #pragma unroll
            for (int nt = 0; nt < 8; nt++) {
                int c = warpN * 64 + nt * 8 + ci * 2;
                float b0 = sbias[256 + c], b1 = sbias[256 + c + 1];
                float w0 = sbias[384 + c], w1 = sbias[384 + c + 1];
                part[mt][0] += silu_f(acc[mt][nt][0] + b0) * w0 + silu_f(acc[mt][nt][1] + b1) * w1;
                part[mt][1] += silu_f(acc[mt][nt][2] + b0) * w0 + silu_f(acc[mt][nt][3] + b1) * w1;
            }
        #pragma unroll
        for (int off = 1; off <= 2; off <<= 1) {
            #pragma unroll
            for (int mt = 0; mt < 2; mt++) {
                part[mt][0] += __shfl_xor_sync(0xFFFFFFFFu, part[mt][0], off);
                part[mt][1] += __shfl_xor_sync(0xFFFFFFFFu, part[mt][1], off);
            }
        }
        if (ci == 0) {
            #pragma unroll
            for (int mt = 0; mt < 2; mt++) {
                int r0 = warpM * 32 + mt * 16 + gr;
                atomicAdd(&s_wsum[r0], part[mt][0]);
                atomicAdd(&s_wsum[r0 + 8], part[mt][1]);
            }
        }
    }

    // scatter m_out + agg from the split stage (m = hi + lo), coalesced v4
    for (int idx = tid; idx < 128 * 32; idx += 256) {
        int e = idx >> 5, q = (idx & 31) * 4;
        uint2 hh = *(const uint2*)(m2h + e * SA2 + q);
        uint2 ll = *(const uint2*)(m2l + e * SA2 + q);
        float v0 = bf2f((unsigned short)(hh.x & 0xFFFFu)) + bf2f((unsigned short)(ll.x & 0xFFFFu));
        float v1 = bf2f((unsigned short)(hh.x >> 16))     + bf2f((unsigned short)(ll.x >> 16));
        float v2 = bf2f((unsigned short)(hh.y & 0xFFFFu)) + bf2f((unsigned short)(ll.y & 0xFFFFu));
        float v3 = bf2f((unsigned short)(hh.y >> 16))     + bf2f((unsigned short)(ll.y >> 16));
        *(float4*)(m_out + (size_t)(eb + e) * 128 + q) = make_float4(v0, v1, v2, v3);
        red4(agg + (size_t)s_row[e] * 128 + q, v0, v1, v2, v3);
    }
    __syncthreads();

    if (tid < 128) {
        float w = s_wsum[tid] + *(float*)(smem + OFF_BC2);
        int r = s_row[tid];
        red4(cs4 + (size_t)r * 4, s_dx[tid] * w, s_dy[tid] * w, s_dz[tid] * w, 1.0f);
    }
}

// ---------------- node kernel (fp32) ----------------
#define NODE_SMEM_BYTES (27136 * 4)
__global__ void __launch_bounds__(256, 1) node_kernel(
    const float* __restrict__ h, const float* __restrict__ coord,
    const float* __restrict__ Wn1, const float* __restrict__ bn1,
    const float* __restrict__ Wn2, const float* __restrict__ bn2,
    const float* __restrict__ agg, const float* __restrict__ cs4,
    float* __restrict__ h_out, float* __restrict__ c_out)
{
    float* smem_f = (float*)dynsmem;
    float* s_nin = smem_f;
    float* s_w   = smem_f + 16640;
    float* s_h1  = smem_f + 18688;
    const int tid = threadIdx.x;
    const int nb = blockIdx.x * 64;
    const int lane = tid & 31;
    const int warp = tid >> 5;
    const int ebase = warp * 8;

    for (int idx = tid; idx < 64 * 64; idx += 256) {
        int n = idx >> 6, f = idx & 63;
        int node = nb + n;
        float4 v = make_float4(0.f, 0.f, 0.f, 0.f);
        if (node < NN) {
            if (f < 32) v = *(const float4*)(h + (size_t)node * 128 + f * 4);
            else        v = *(const float4*)(agg + (size_t)node * 128 + (f - 32) * 4);
        }
        *(float4*)&s_nin[n * 260 + f * 4] = v;
    }
    __syncthreads();

    float acc[8][4];
    #pragma unroll
    for (int i = 0; i < 8; i++)
        #pragma unroll
        for (int j = 0; j < 4; j++) acc[i][j] = 0.0f;

    for (int kb = 0; kb < 256; kb += 16) {
        for (int idx = tid; idx < 2048; idx += 256) s_w[idx] = Wn1[kb * 128 + idx];
        __syncthreads();
        #pragma unroll
        for (int k = 0; k < 16; k++) {
            float4 b = *(const float4*)&s_w[k * 128 + lane * 4];
            float bv[4] = {b.x, b.y, b.z, b.w};
            float av[8];
            #pragma unroll
            for (int i = 0; i < 8; i++) av[i] = s_nin[(ebase + i) * 260 + kb + k];
            #pragma unroll
            for (int i = 0; i < 8; i++)
                #pragma unroll
                for (int j = 0; j < 4; j++) acc[i][j] = fmaf(av[i], bv[j], acc[i][j]);
        }
        __syncthreads();
    }
    {
        float4 b1 = *(const float4*)&bn1[lane * 4];
        float bv[4] = {b1.x, b1.y, b1.z, b1.w};
        #pragma unroll
        for (int i = 0; i < 8; i++) {
            float4 o;
            o.x = silu_f(acc[i][0] + bv[0]); o.y = silu_f(acc[i][1] + bv[1]);
            o.z = silu_f(acc[i][2] + bv[2]); o.w = silu_f(acc[i][3] + bv[3]);
            *(float4*)&s_h1[(ebase + i) * 132 + lane * 4] = o;
        }
    }
    #pragma unroll
    for (int i = 0; i < 8; i++)
        #pragma unroll
        for (int j = 0; j < 4; j++) acc[i][j] = 0.0f;

    for (int kb = 0; kb < 128; kb += 16) {
        for (int idx = tid; idx < 2048; idx += 256) s_w[idx] = Wn2[kb * 128 + idx];
        __syncthreads();
        #pragma unroll
        for (int k = 0; k < 16; k++) {
            float4 b = *(const float4*)&s_w[k * 128 + lane * 4];
            float bv[4] = {b.x, b.y, b.z, b.w};
            float av[8];
            #pragma unroll
            for (int i = 0; i < 8; i++) av[i] = s_h1[(ebase + i) * 132 + kb + k];
            #pragma unroll
            for (int i = 0; i < 8; i++)
                #pragma unroll
                for (int j = 0; j < 4; j++) acc[i][j] = fmaf(av[i], bv[j], acc[i][j]);
        }
        __syncthreads();
    }
    {
        float4 b2 = *(const float4*)&bn2[lane * 4];
        #pragma unroll
        for (int i = 0; i < 8; i++) {
            int node = nb + ebase + i;
            if (node < NN) {
                float4 o;
                o.x = acc[i][0] + b2.x; o.y = acc[i][1] + b2.y;
                o.z = acc[i][2] + b2.z; o.w = acc[i][3] + b2.w;
                *(float4*)&h_out[(size_t)node * 128 + lane * 4] = o;
            }
        }
    }
    if (tid < 64) {
        int node = nb + tid;
        if (node < NN) {
            float4 s = *(const float4*)(cs4 + (size_t)node * 4);
            float dn = fmaxf(s.w, 1.0f);
            c_out[node * 3 + 0] = coord[node * 3 + 0] + s.x / dn;
            c_out[node * 3 + 1] = coord[node * 3 + 1] + s.y / dn;
            c_out[node * 3 + 2] = coord[node * 3 + 2] + s.z / dn;
        }
    }
}

extern "C" void kernel_launch(void* const* d_in, const int* in_sizes, int n_in,
                              void* d_out, int out_size)
{
    const float* h     = (const float*)d_in[0];
    const float* coord = (const float*)d_in[1];
    const float* eattr = (const float*)d_in[2];
    const int*   ei    = (const int*)d_in[3];
    const float* We1 = (const float*)d_in[4];
    const float* be1 = (const float*)d_in[5];
    const float* We2 = (const float*)d_in[6];
    const float* be2 = (const float*)d_in[7];
    const float* Wn1 = (const float*)d_in[8];
    const float* bn1 = (const float*)d_in[9];
    const float* Wn2 = (const float*)d_in[10];
    const float* bn2 = (const float*)d_in[11];
    const float* Wc1 = (const float*)d_in[12];
    const float* bc1 = (const float*)d_in[13];
    const float* Wc2 = (const float*)d_in[14];
    const float* bc2 = (const float*)d_in[15];

    float* out   = (float*)d_out;
    float* h_out = out;
    float* c_out = out + (size_t)NN * 128;
    float* m_out = c_out + (size_t)NN * 3;

    void *p_agg, *p_cs4;
    cudaGetSymbolAddress(&p_agg, g_agg);
    cudaGetSymbolAddress(&p_cs4, g_cs4);
    cudaMemsetAsync(p_agg, 0, (size_t)NN * 128 * sizeof(float), 0);
    cudaMemsetAsync(p_cs4, 0, (size_t)NN * 4 * sizeof(float), 0);

    prep_h_kernel<<<(NN * 128 + 255) / 256, 256>>>(h);
    prep_w_kernel<<<128, 256>>>(We1, We2, Wc1);

    cudaFuncSetAttribute(h1_kernel, cudaFuncAttributeMaxDynamicSharedMemorySize, H1_SMEM);
    cudaFuncSetAttribute(edge_kernel, cudaFuncAttributeMaxDynamicSharedMemorySize, EDGE_SMEM);
    cudaFuncSetAttribute(node_kernel, cudaFuncAttributeMaxDynamicSharedMemorySize, NODE_SMEM_BYTES);

    h1_kernel<<<(NN + 127) / 128, 256, H1_SMEM>>>();

    edge_kernel<<<NE / 128, 256, EDGE_SMEM>>>(
        coord, eattr, ei, We1, be1, be2, bc1, Wc2, bc2,
        m_out, (float*)p_agg, (float*)p_cs4);

    node_kernel<<<(NN + 63) / 64, 256, NODE_SMEM_BYTES>>>(
        h, coord, Wn1, bn1, Wn2, bn2,
        (const float*)p_agg, (const float*)p_cs4, h_out, c_out);
}

// round 7
// speedup vs baseline: 4.0394x; 1.2497x over previous
#include <cuda_runtime.h>
#include <cuda_fp16.h>
#include <stdint.h>

#define NN 50000
#define NE 800000

// ---------------- device scratch ----------------
__device__ float g_agg[(size_t)NN * 128];
__device__ float g_cs4[(size_t)NN * 4];          // {sum dx*w, dy*w, dz*w, cnt}
__device__ float g_H1a[(size_t)NN * 128];
__device__ float g_H1b[(size_t)NN * 128];
__device__ uint32_t g_hpack[(size_t)NN * 128];   // (lo16<<16)|hi16 fp16 split of h
__device__ uint32_t g_W1ahi[128 * 64], g_W1alo[128 * 64];
__device__ uint32_t g_W1bhi[128 * 64], g_W1blo[128 * 64];
__device__ uint32_t g_W2hi[128 * 64],  g_W2lo[128 * 64];
__device__ uint32_t g_W3hi[128 * 64],  g_W3lo[128 * 64];

__device__ __forceinline__ unsigned short f2h(float x) {
    __half v = __float2half(x);
    return *reinterpret_cast<unsigned short*>(&v);
}
__device__ __forceinline__ float h2f(unsigned short u) {
    __half v = *reinterpret_cast<__half*>(&u);
    return __half2float(v);
}
__device__ __forceinline__ float silu_f(float x) { return x / (1.0f + __expf(-x)); }
__device__ __forceinline__ void red4(float* p, float a, float b, float c, float d) {
    asm volatile("red.global.add.v4.f32 [%0], {%1,%2,%3,%4};"
                 :: "l"(p), "f"(a), "f"(b), "f"(c), "f"(d) : "memory");
}
__device__ __forceinline__ void red2(float* p, float a, float b) {
    asm volatile("red.global.add.v2.f32 [%0], {%1,%2};" :: "l"(p), "f"(a), "f"(b) : "memory");
}
__device__ __forceinline__ uint32_t smem_u32(const void* p) {
    uint32_t a;
    asm("{ .reg .u64 t; cvta.to.shared.u64 t, %1; cvt.u32.u64 %0, t; }" : "=r"(a) : "l"(p));
    return a;
}
__device__ __forceinline__ void cp16(uint32_t dst, const void* src) {
    asm volatile("cp.async.ca.shared.global [%0], [%1], 16;" :: "r"(dst), "l"(src));
}
__device__ __forceinline__ void cp_commit() {
    asm volatile("cp.async.commit_group;" ::: "memory");
}
__device__ __forceinline__ void wg0() { asm volatile("cp.async.wait_group 0;" ::: "memory"); }
__device__ __forceinline__ void wg1() { asm volatile("cp.async.wait_group 1;" ::: "memory"); }
__device__ __forceinline__ void ldsm4(uint32_t* r, uint32_t addr) {
    asm volatile("ldmatrix.sync.aligned.m8n8.x4.shared.b16 {%0,%1,%2,%3}, [%4];"
        : "=r"(r[0]), "=r"(r[1]), "=r"(r[2]), "=r"(r[3]) : "r"(addr));
}
#define MMAH(ac, a, b0, b1) \
    asm volatile("mma.sync.aligned.m16n8k16.row.col.f32.f16.f16.f32 " \
        "{%0,%1,%2,%3}, {%4,%5,%6,%7}, {%8,%9}, {%0,%1,%2,%3};" \
        : "+f"((ac)[0]), "+f"((ac)[1]), "+f"((ac)[2]), "+f"((ac)[3]) \
        : "r"((a)[0]), "r"((a)[1]), "r"((a)[2]), "r"((a)[3]), "r"(b0), "r"(b1))

#define SA2 136
#define B_BUF_ST 20480u
#define B_HL_ST  10240u
// edge smem layout (bytes)
#define MH        0u          // A fp16 hi [128][136] u16 = 34816
#define E_OFFB    34816u      // B ring: 2 x 20480
#define OFF_W1C   75776u      // [17][128] f32 = 8704
#define OFF_BIAS  84480u      // 512 f
#define OFF_ROW   86528u
#define OFF_COL   87040u
#define OFF_D     87552u
#define OFF_RAD   89088u
#define OFF_WSUM  89600u
#define OFF_BC2   90112u
#define EDGE_SMEM 90144u
// h1 smem layout
#define H1_AH     0u
#define H1_AL     34816u
#define H1_OFFB   69632u
#define H1_SMEM   110592u

extern __shared__ char dynsmem[];

// ---------------- prep ----------------
__global__ void prep_h_kernel(const float* __restrict__ h) {
    size_t i = (size_t)blockIdx.x * 256 + threadIdx.x;
    if (i < (size_t)NN * 128) {
        float v = h[i];
        unsigned short hi = f2h(v);
        unsigned short lo = f2h(v - h2f(hi));
        g_hpack[i] = (uint32_t)hi | ((uint32_t)lo << 16);
    }
}
__global__ void prep_w_kernel(const float* __restrict__ We1,
                              const float* __restrict__ We2,
                              const float* __restrict__ Wc1) {
    int t = blockIdx.x * 256 + threadIdx.x;
    if (t >= 32768) return;
    int img = t >> 13, u = t & 8191, n = u >> 6, kp = u & 63;
    int k0 = kp * 2, k1 = k0 + 1;
    float v0, v1; uint32_t *dh, *dl;
    if (img == 0)      { v0 = We1[k0 * 128 + n];         v1 = We1[k1 * 128 + n];
                         dh = g_W1ahi; dl = g_W1alo; }
    else if (img == 1) { v0 = We1[(128 + k0) * 128 + n]; v1 = We1[(128 + k1) * 128 + n];
                         dh = g_W1bhi; dl = g_W1blo; }
    else if (img == 2) { v0 = We2[k0 * 128 + n];         v1 = We2[k1 * 128 + n];
                         dh = g_W2hi; dl = g_W2lo; }
    else               { v0 = Wc1[k0 * 128 + n];         v1 = Wc1[k1 * 128 + n];
                         dh = g_W3hi; dl = g_W3lo; }
    unsigned short h0 = f2h(v0), h1 = f2h(v1);
    *(dh + n * 64 + kp) = (uint32_t)h0 | ((uint32_t)h1 << 16);
    *(dl + n * 64 + kp) = (uint32_t)f2h(v0 - h2f(h0)) | ((uint32_t)f2h(v1 - h2f(h1)) << 16);
}

// ---------------- GEMM machinery ----------------
__device__ __forceinline__ void issue_chunk(uint32_t sb, uint32_t offB, int buf,
                                            const uint32_t* gHi, const uint32_t* gLo, int kb) {
    int tid = threadIdx.x;
    #pragma unroll
    for (int j = 0; j < 4; j++) {
        int g = tid + 256 * j;
        int arr = g >> 9;
        int n = (g >> 2) & 127;
        int q = g & 3;
        const uint32_t* src = (arr ? gLo : gHi) + n * 64 + (kb >> 1) + q * 4;
        uint32_t dst = sb + offB + (uint32_t)buf * B_BUF_ST + (uint32_t)arr * B_HL_ST
                     + (uint32_t)(n * 20 + q * 4) * 4u;
        cp16(dst, src);
    }
    cp_commit();
}

__device__ __forceinline__ void mma_step(uint32_t aBaseH, uint32_t aBaseL, bool three,
                                         int kb, uint32_t bBase, int kloc,
                                         int warpM, int warpN, int lane,
                                         float acc[2][8][4]) {
    uint32_t ah[2][4], al[2][4];
    const uint32_t arow = (uint32_t)(warpM * 32 + (lane & 15));
    const uint32_t aoff = (uint32_t)(kb + ((lane >> 4) << 3)) * 2u;
    #pragma unroll
    for (int mt = 0; mt < 2; mt++) {
        uint32_t ad = (arow + (uint32_t)(mt * 16)) * (SA2 * 2u) + aoff;
        ldsm4(ah[mt], aBaseH + ad);
        if (three) ldsm4(al[mt], aBaseL + ad);
    }
    const uint32_t nrow = (uint32_t)(warpN * 64 + (lane & 7) + ((lane >> 4) << 3));
    const uint32_t boffk = (uint32_t)((kloc >> 1) + ((lane >> 3) & 1) * 4) * 4u;
    #pragma unroll
    for (int p = 0; p < 4; p++) {
        uint32_t bh[4], bl[4];
        uint32_t bd = (nrow + (uint32_t)(p * 16)) * 80u + boffk;
        ldsm4(bh, bBase + bd);
        ldsm4(bl, bBase + B_HL_ST + bd);
        int nt0 = p * 2, nt1 = p * 2 + 1;
        #pragma unroll
        for (int mt = 0; mt < 2; mt++) {
            MMAH(acc[mt][nt0], ah[mt], bh[0], bh[1]);
            MMAH(acc[mt][nt0], ah[mt], bl[0], bl[1]);
            if (three) MMAH(acc[mt][nt0], al[mt], bh[0], bh[1]);
            MMAH(acc[mt][nt1], ah[mt], bh[2], bh[3]);
            MMAH(acc[mt][nt1], ah[mt], bl[2], bl[3]);
            if (three) MMAH(acc[mt][nt1], al[mt], bh[2], bh[3]);
        }
    }
}

// pipelined K=128 pass; caller must have issued chunks 0,1 already.
// On exit (if !last): next-gemm chunks 0,1 are in flight.
__device__ __forceinline__ void gemm_loop(uint32_t sb, uint32_t offAh, uint32_t offAl,
    bool three, uint32_t offB,
    const uint32_t* gHi, const uint32_t* gLo,
    const uint32_t* nHi, const uint32_t* nLo, bool last,
    int warpM, int warpN, int lane, float acc[2][8][4]) {
    const uint32_t aH = sb + offAh, aL = sb + offAl;
    for (int c = 0; c < 4; c++) {
        if (c == 3 && last) wg0(); else wg1();
        __syncthreads();
        uint32_t bB = sb + offB + (uint32_t)(c & 1) * B_BUF_ST;
        mma_step(aH, aL, three, c * 32,      bB, 0,  warpM, warpN, lane, acc);
        mma_step(aH, aL, three, c * 32 + 16, bB, 16, warpM, warpN, lane, acc);
        __syncthreads();
        if (c < 2)      issue_chunk(sb, offB, c & 1, gHi, gLo, (c + 2) * 32);
        else if (!last) issue_chunk(sb, offB, c & 1, nHi, nLo, (c - 2) * 32);
    }
}

// ---------------- H1 precompute kernel (3-term fp16, near-exact) ----------------
__global__ void __launch_bounds__(256, 2) h1_kernel() {
    char* smem = dynsmem;
    const uint32_t sb = smem_u32(smem);
    const int tid = threadIdx.x;
    const int lane = tid & 31, wid = tid >> 5;
    const int warpM = wid & 3, warpN = wid >> 2;
    const int gr = lane >> 2, ci = lane & 3;
    const int nb = blockIdx.x * 128;

    uint16_t* aH = (uint16_t*)(smem + H1_AH);
    uint16_t* aL = (uint16_t*)(smem + H1_AL);
    {
        int e = tid >> 1, half = tid & 1;
        int node = nb + e; if (node >= NN) node = NN - 1;
        const uint4* hp = (const uint4*)(g_hpack + (size_t)node * 128 + half * 64);
        #pragma unroll 4
        for (int j0 = 0; j0 < 64; j0 += 8) {
            uint4 v0 = hp[j0 >> 2], v1 = hp[(j0 >> 2) + 1];
            uint4 h4, l4;
            h4.x = (v0.x & 0xFFFFu) | (v0.y << 16);  l4.x = (v0.x >> 16) | (v0.y & 0xFFFF0000u);
            h4.y = (v0.z & 0xFFFFu) | (v0.w << 16);  l4.y = (v0.z >> 16) | (v0.w & 0xFFFF0000u);
            h4.z = (v1.x & 0xFFFFu) | (v1.y << 16);  l4.z = (v1.x >> 16) | (v1.y & 0xFFFF0000u);
            h4.w = (v1.z & 0xFFFFu) | (v1.w << 16);  l4.w = (v1.z >> 16) | (v1.w & 0xFFFF0000u);
            int o = e * SA2 + half * 64 + j0;
            *(uint4*)(aH + o) = h4;
            *(uint4*)(aL + o) = l4;
        }
    }
    issue_chunk(sb, H1_OFFB, 0, g_W1ahi, g_W1alo, 0);
    issue_chunk(sb, H1_OFFB, 1, g_W1ahi, g_W1alo, 32);

    float acc[2][8][4];
    #pragma unroll
    for (int a = 0; a < 2; a++)
        #pragma unroll
        for (int b = 0; b < 8; b++)
            #pragma unroll
            for (int d = 0; d < 4; d++) acc[a][b][d] = 0.0f;

    gemm_loop(sb, H1_AH, H1_AL, true, H1_OFFB, g_W1ahi, g_W1alo,
              g_W1bhi, g_W1blo, false, warpM, warpN, lane, acc);
    #pragma unroll
    for (int mt = 0; mt < 2; mt++) {
        int row = nb + warpM * 32 + mt * 16 + gr;
        #pragma unroll
        for (int nt = 0; nt < 8; nt++) {
            int c = warpN * 64 + nt * 8 + ci * 2;
            if (row < NN)
                *(float2*)(g_H1a + (size_t)row * 128 + c) = make_float2(acc[mt][nt][0], acc[mt][nt][1]);
            if (row + 8 < NN)
                *(float2*)(g_H1a + (size_t)(row + 8) * 128 + c) = make_float2(acc[mt][nt][2], acc[mt][nt][3]);
            acc[mt][nt][0] = acc[mt][nt][1] = acc[mt][nt][2] = acc[mt][nt][3] = 0.0f;
        }
    }
    gemm_loop(sb, H1_AH, H1_AL, true, H1_OFFB, g_W1bhi, g_W1blo,
              nullptr, nullptr, true, warpM, warpN, lane, acc);
    #pragma unroll
    for (int mt = 0; mt < 2; mt++) {
        int row = nb + warpM * 32 + mt * 16 + gr;
        #pragma unroll
        for (int nt = 0; nt < 8; nt++) {
            int c = warpN * 64 + nt * 8 + ci * 2;
            if (row < NN)
                *(float2*)(g_H1b + (size_t)row * 128 + c) = make_float2(acc[mt][nt][0], acc[mt][nt][1]);
            if (row + 8 < NN)
                *(float2*)(g_H1b + (size_t)(row + 8) * 128 + c) = make_float2(acc[mt][nt][2], acc[mt][nt][3]);
        }
    }
}

// ---------------- edge kernel ----------------
__global__ void __launch_bounds__(256, 2) edge_kernel(
    const float* __restrict__ coord, const float* __restrict__ eattr,
    const int* __restrict__ ei, const float* __restrict__ We1,
    const float* __restrict__ be1, const float* __restrict__ be2,
    const float* __restrict__ bc1, const float* __restrict__ Wc2,
    const float* __restrict__ bc2,
    float* __restrict__ m_out, float* __restrict__ agg, float* __restrict__ cs4)
{
    char* smem = dynsmem;
    const uint32_t sb = smem_u32(smem);
    const int tid = threadIdx.x;
    const int lane = tid & 31, wid = tid >> 5;
    const int warpM = wid & 3, warpN = wid >> 2;
    const int gr = lane >> 2, ci = lane & 3;
    const int eb = blockIdx.x * 128;

    uint16_t* mh  = (uint16_t*)(smem + MH);
    float* w1c    = (float*)(smem + OFF_W1C);
    float* sbias  = (float*)(smem + OFF_BIAS);
    int* s_row    = (int*)(smem + OFF_ROW);
    int* s_col    = (int*)(smem + OFF_COL);
    float* s_dx   = (float*)(smem + OFF_D);
    float* s_dy   = s_dx + 128;
    float* s_dz   = s_dx + 256;
    float* s_rad  = (float*)(smem + OFF_RAD);
    float* s_wsum = (float*)(smem + OFF_WSUM);

    for (int i = tid; i < 17 * 128; i += 256) w1c[i] = We1[256 * 128 + i];
    if (tid < 128) {
        sbias[tid] = be1[tid]; sbias[128 + tid] = be2[tid];
        sbias[256 + tid] = bc1[tid]; sbias[384 + tid] = Wc2[tid];
        s_wsum[tid] = 0.0f;
    }
    if (tid == 0) *(float*)(smem + OFF_BC2) = bc2[0];
    if (tid < 128) {
        int g = eb + tid;
        int r = ei[g], c = ei[NE + g];
        s_row[tid] = r; s_col[tid] = c;
        float dx = coord[r * 3 + 0] - coord[c * 3 + 0];
        float dy = coord[r * 3 + 1] - coord[c * 3 + 1];
        float dz = coord[r * 3 + 2] - coord[c * 3 + 2];
        s_dx[tid] = dx; s_dy[tid] = dy; s_dz[tid] = dz;
        s_rad[tid] = dx * dx + dy * dy + dz * dz;
    }
    // prefetch GEMM2 chunks 0,1 behind the pre-phase
    issue_chunk(sb, E_OFFB, 0, g_W2hi, g_W2lo, 0);
    issue_chunk(sb, E_OFFB, 1, g_W2hi, g_W2lo, 32);
    __syncthreads();

    // pre phase: m1 = silu(H1a[row] + H1b[col] + be1 + [rad|eattr]@We1c) -> fp16
    {
        int e = tid >> 1, half = tid & 1;
        int r = s_row[e], c = s_col[e];
        float x[17];
        x[0] = s_rad[e];
        const float* ea = eattr + (size_t)(eb + e) * 16;
        #pragma unroll
        for (int j = 0; j < 16; j++) x[j + 1] = ea[j];
        const float4* pa = (const float4*)(g_H1a + (size_t)r * 128 + half * 64);
        const float4* pb = (const float4*)(g_H1b + (size_t)c * 128 + half * 64);
        #pragma unroll
        for (int cb = 0; cb < 4; cb++) {
            int cc0 = half * 64 + cb * 16;
            float pre[16];
            #pragma unroll
            for (int i = 0; i < 4; i++) {
                float4 va = pa[cb * 4 + i], vb = pb[cb * 4 + i];
                pre[i * 4 + 0] = va.x + vb.x + sbias[cc0 + i * 4 + 0];
                pre[i * 4 + 1] = va.y + vb.y + sbias[cc0 + i * 4 + 1];
                pre[i * 4 + 2] = va.z + vb.z + sbias[cc0 + i * 4 + 2];
                pre[i * 4 + 3] = va.w + vb.w + sbias[cc0 + i * 4 + 3];
            }
            #pragma unroll
            for (int j = 0; j < 17; j++) {
                float xj = x[j];
                #pragma unroll
                for (int i = 0; i < 16; i++)
                    pre[i] = fmaf(xj, w1c[j * 128 + cc0 + i], pre[i]);
            }
            #pragma unroll
            for (int i = 0; i < 16; i += 2) {
                float s0 = silu_f(pre[i]), s1 = silu_f(pre[i + 1]);
                *(uint32_t*)(mh + e * SA2 + cc0 + i) =
                    (uint32_t)f2h(s0) | ((uint32_t)f2h(s1) << 16);
            }
        }
    }
    // (gemm_loop's first barrier orders mh writes vs mma reads)

    float acc[2][8][4];
    #pragma unroll
    for (int a = 0; a < 2; a++)
        #pragma unroll
        for (int b = 0; b < 8; b++)
            #pragma unroll
            for (int d = 0; d < 4; d++) acc[a][b][d] = 0.0f;

    // ---- GEMM2: m1 @ We2 (prefetches GEMM3 chunks at tail) ----
    gemm_loop(sb, MH, 0u, false, E_OFFB, g_W2hi, g_W2lo,
              g_W3hi, g_W3lo, false, warpM, warpN, lane, acc);

    // epilogue 2: m = silu(+be2); fp32 m_out + agg from registers; fp16 -> mh for GEMM3
    #pragma unroll
    for (int mt = 0; mt < 2; mt++) {
        int e0 = warpM * 32 + mt * 16 + gr, e1 = e0 + 8;
        int row0 = s_row[e0], row1 = s_row[e1];
        #pragma unroll
        for (int nt = 0; nt < 8; nt++) {
            int c = warpN * 64 + nt * 8 + ci * 2;
            float b0 = sbias[128 + c], b1 = sbias[128 + c + 1];
            float x0 = silu_f(acc[mt][nt][0] + b0), x1 = silu_f(acc[mt][nt][1] + b1);
            float x2 = silu_f(acc[mt][nt][2] + b0), x3 = silu_f(acc[mt][nt][3] + b1);
            *(float2*)(m_out + (size_t)(eb + e0) * 128 + c) = make_float2(x0, x1);
            *(float2*)(m_out + (size_t)(eb + e1) * 128 + c) = make_float2(x2, x3);
            red2(agg + (size_t)row0 * 128 + c, x0, x1);
            red2(agg + (size_t)row1 * 128 + c, x2, x3);
            *(uint32_t*)(mh + e0 * SA2 + c) = (uint32_t)f2h(x0) | ((uint32_t)f2h(x1) << 16);
            *(uint32_t*)(mh + e1 * SA2 + c) = (uint32_t)f2h(x2) | ((uint32_t)f2h(x3) << 16);
            acc[mt][nt][0] = acc[mt][nt][1] = acc[mt][nt][2] = acc[mt][nt][3] = 0.0f;
        }
    }

    // ---- GEMM3: m @ Wc1 ----
    gemm_loop(sb, MH, 0u, false, E_OFFB, g_W3hi, g_W3lo,
              nullptr, nullptr, true, warpM, warpN, lane, acc);

    // epilogue 3: per-edge coord weight
    {
        float part[2][2] = {{0.f, 0.f}, {0.f, 0.f}};
        #pragma unroll
        for (int mt = 0; mt < 2; mt++)
            #pragma unroll
            for (int nt = 0; nt < 8; nt++) {
                int c = warpN * 64 + nt * 8 + ci * 2;
                float b0 = sbias[256 + c], b1 = sbias[256 + c + 1];
                float w0 = sbias[384 + c], w1 = sbias[384 + c + 1];
                part[mt][0] += silu_f(acc[mt][nt][0] + b0) * w0 + silu_f(acc[mt][nt][1] + b1) * w1;
                part[mt][1] += silu_f(acc[mt][nt][2] + b0) * w0 + silu_f(acc[mt][nt][3] + b1) * w1;
            }
        #pragma unroll
        for (int off = 1; off <= 2; off <<= 1) {
            #pragma unroll
            for (int mt = 0; mt < 2; mt++) {
                part[mt][0] += __shfl_xor_sync(0xFFFFFFFFu, part[mt][0], off);
                part[mt][1] += __shfl_xor_sync(0xFFFFFFFFu, part[mt][1], off);
            }
        }
        if (ci == 0) {
            #pragma unroll
            for (int mt = 0; mt < 2; mt++) {
                int r0 = warpM * 32 + mt * 16 + gr;
                atomicAdd(&s_wsum[r0], part[mt][0]);
                atomicAdd(&s_wsum[r0 + 8], part[mt][1]);
            }
        }
    }
    __syncthreads();

    if (tid < 128) {
        float w = s_wsum[tid] + *(float*)(smem + OFF_BC2);
        int r = s_row[tid];
        red4(cs4 + (size_t)r * 4, s_dx[tid] * w, s_dy[tid] * w, s_dz[tid] * w, 1.0f);
    }
}

// ---------------- node kernel (fp32) ----------------
#define NODE_SMEM_BYTES (27136 * 4)
__global__ void __launch_bounds__(256, 2) node_kernel(
    const float* __restrict__ h, const float* __restrict__ coord,
    const float* __restrict__ Wn1, const float* __restrict__ bn1,
    const float* __restrict__ Wn2, const float* __restrict__ bn2,
    const float* __restrict__ agg, const float* __restrict__ cs4,
    float* __restrict__ h_out, float* __restrict__ c_out)
{
    float* smem_f = (float*)dynsmem;
    float* s_nin = smem_f;
    float* s_w   = smem_f + 16640;
    float* s_h1  = smem_f + 18688;
    const int tid = threadIdx.x;
    const int nb = blockIdx.x * 64;
    const int lane = tid & 31;
    const int warp = tid >> 5;
    const int ebase = warp * 8;

    for (int idx = tid; idx < 64 * 64; idx += 256) {
        int n = idx >> 6, f = idx & 63;
        int node = nb + n;
        float4 v = make_float4(0.f, 0.f, 0.f, 0.f);
        if (node < NN) {
            if (f < 32) v = *(const float4*)(h + (size_t)node * 128 + f * 4);
            else        v = *(const float4*)(agg + (size_t)node * 128 + (f - 32) * 4);
        }
        *(float4*)&s_nin[n * 260 + f * 4] = v;
    }
    __syncthreads();

    float acc[8][4];
    #pragma unroll
    for (int i = 0; i < 8; i++)
        #pragma unroll
        for (int j = 0; j < 4; j++) acc[i][j] = 0.0f;

    for (int kb = 0; kb < 256; kb += 16) {
        for (int idx = tid; idx < 2048; idx += 256) s_w[idx] = Wn1[kb * 128 + idx];
        __syncthreads();
        #pragma unroll
        for (int k = 0; k < 16; k++) {
            float4 b = *(const float4*)&s_w[k * 128 + lane * 4];
            float bv[4] = {b.x, b.y, b.z, b.w};
            float av[8];
            #pragma unroll
            for (int i = 0; i < 8; i++) av[i] = s_nin[(ebase + i) * 260 + kb + k];
            #pragma unroll
            for (int i = 0; i < 8; i++)
                #pragma unroll
                for (int j = 0; j < 4; j++) acc[i][j] = fmaf(av[i], bv[j], acc[i][j]);
        }
        __syncthreads();
    }
    {
        float4 b1 = *(const float4*)&bn1[lane * 4];
        float bv[4] = {b1.x, b1.y, b1.z, b1.w};
        #pragma unroll
        for (int i = 0; i < 8; i++) {
            float4 o;
            o.x = silu_f(acc[i][0] + bv[0]); o.y = silu_f(acc[i][1] + bv[1]);
            o.z = silu_f(acc[i][2] + bv[2]); o.w = silu_f(acc[i][3] + bv[3]);
            *(float4*)&s_h1[(ebase + i) * 132 + lane * 4] = o;
        }
    }
    #pragma unroll
    for (int i = 0; i < 8; i++)
        #pragma unroll
        for (int j = 0; j < 4; j++) acc[i][j] = 0.0f;

    for (int kb = 0; kb < 128; kb += 16) {
        for (int idx = tid; idx < 2048; idx += 256) s_w[idx] = Wn2[kb * 128 + idx];
        __syncthreads();
        #pragma unroll
        for (int k = 0; k < 16; k++) {
            float4 b = *(const float4*)&s_w[k * 128 + lane * 4];
            float bv[4] = {b.x, b.y, b.z, b.w};
            float av[8];
            #pragma unroll
            for (int i = 0; i < 8; i++) av[i] = s_h1[(ebase + i) * 132 + kb + k];
            #pragma unroll
            for (int i = 0; i < 8; i++)
                #pragma unroll
                for (int j = 0; j < 4; j++) acc[i][j] = fmaf(av[i], bv[j], acc[i][j]);
        }
        __syncthreads();
    }
    {
        float4 b2 = *(const float4*)&bn2[lane * 4];
        #pragma unroll
        for (int i = 0; i < 8; i++) {
            int node = nb + ebase + i;
            if (node < NN) {
                float4 o;
                o.x = acc[i][0] + b2.x; o.y = acc[i][1] + b2.y;
                o.z = acc[i][2] + b2.z; o.w = acc[i][3] + b2.w;
                *(float4*)&h_out[(size_t)node * 128 + lane * 4] = o;
            }
        }
    }
    if (tid < 64) {
        int node = nb + tid;
        if (node < NN) {
            float4 s = *(const float4*)(cs4 + (size_t)node * 4);
            float dn = fmaxf(s.w, 1.0f);
            c_out[node * 3 + 0] = coord[node * 3 + 0] + s.x / dn;
            c_out[node * 3 + 1] = coord[node * 3 + 1] + s.y / dn;
            c_out[node * 3 + 2] = coord[node * 3 + 2] + s.z / dn;
        }
    }
}

extern "C" void kernel_launch(void* const* d_in, const int* in_sizes, int n_in,
                              void* d_out, int out_size)
{
    const float* h     = (const float*)d_in[0];
    const float* coord = (const float*)d_in[1];
    const float* eattr = (const float*)d_in[2];
    const int*   ei    = (const int*)d_in[3];
    const float* We1 = (const float*)d_in[4];
    const float* be1 = (const float*)d_in[5];
    const float* We2 = (const float*)d_in[6];
    const float* be2 = (const float*)d_in[7];
    const float* Wn1 = (const float*)d_in[8];
    const float* bn1 = (const float*)d_in[9];
    const float* Wn2 = (const float*)d_in[10];
    const float* bn2 = (const float*)d_in[11];
    const float* Wc1 = (const float*)d_in[12];
    const float* bc1 = (const float*)d_in[13];
    const float* Wc2 = (const float*)d_in[14];
    const float* bc2 = (const float*)d_in[15];

    float* out   = (float*)d_out;
    float* h_out = out;
    float* c_out = out + (size_t)NN * 128;
    float* m_out = c_out + (size_t)NN * 3;

    void *p_agg, *p_cs4;
    cudaGetSymbolAddress(&p_agg, g_agg);
    cudaGetSymbolAddress(&p_cs4, g_cs4);
    cudaMemsetAsync(p_agg, 0, (size_t)NN * 128 * sizeof(float), 0);
    cudaMemsetAsync(p_cs4, 0, (size_t)NN * 4 * sizeof(float), 0);

    prep_h_kernel<<<(NN * 128 + 255) / 256, 256>>>(h);
    prep_w_kernel<<<128, 256>>>(We1, We2, Wc1);

    cudaFuncSetAttribute(h1_kernel, cudaFuncAttributeMaxDynamicSharedMemorySize, H1_SMEM);
    cudaFuncSetAttribute(edge_kernel, cudaFuncAttributeMaxDynamicSharedMemorySize, EDGE_SMEM);
    cudaFuncSetAttribute(node_kernel, cudaFuncAttributeMaxDynamicSharedMemorySize, NODE_SMEM_BYTES);

    h1_kernel<<<(NN + 127) / 128, 256, H1_SMEM>>>();

    edge_kernel<<<NE / 128, 256, EDGE_SMEM>>>(
        coord, eattr, ei, We1, be1, be2, bc1, Wc2, bc2,
        m_out, (float*)p_agg, (float*)p_cs4);

    node_kernel<<<(NN + 63) / 64, 256, NODE_SMEM_BYTES>>>(
        h, coord, Wn1, bn1, Wn2, bn2,
        (const float*)p_agg, (const float*)p_cs4, h_out, c_out);
}